// round 2
// baseline (speedup 1.0000x reference)
#include <cuda_runtime.h>
#include <mma.h>
#include <cstdint>

using namespace nvcuda;

#define NNODES 50000
#define NEDGES 800000
#define TOTEDGES (NEDGES + NNODES)
#define NEG_SLOPE 0.2f

// ---------------- scratch (allocation-free: device globals) ----------------
__device__ float g_h0[(size_t)NNODES * 128];
__device__ float g_h1[(size_t)NNODES * 128];
__device__ float g_s[NNODES * 2];
__device__ float g_t[NNODES * 2];
__device__ int   g_deg[NNODES];
__device__ int   g_rowptr[NNODES + 1];
__device__ int   g_cursor[NNODES];
__device__ int   g_col[TOTEDGES];

// ---------------- CSR build ----------------
__global__ void k_init_deg(int* __restrict__ deg, int n) {
    int i = blockIdx.x * blockDim.x + threadIdx.x;
    if (i < n) deg[i] = 1;  // self loop
}

__global__ void k_hist(const int* __restrict__ ei, int e, int* __restrict__ deg) {
    int i = blockIdx.x * blockDim.x + threadIdx.x;
    if (i < e) atomicAdd(&deg[ei[e + i]], 1);  // dst row
}

__global__ void k_scan(const int* __restrict__ deg, int* __restrict__ rowptr, int n) {
    __shared__ int sh[1024];
    __shared__ int s_run;
    int tid = threadIdx.x;
    if (tid == 0) s_run = 0;
    __syncthreads();
    for (int base = 0; base < n; base += 1024) {
        int v = (base + tid < n) ? deg[base + tid] : 0;
        sh[tid] = v;
        __syncthreads();
        for (int off = 1; off < 1024; off <<= 1) {
            int t = (tid >= off) ? sh[tid - off] : 0;
            __syncthreads();
            sh[tid] += t;
            __syncthreads();
        }
        if (base + tid < n) rowptr[base + tid + 1] = s_run + sh[tid];
        __syncthreads();
        if (tid == 0) s_run += sh[1023];
        __syncthreads();
    }
    if (tid == 0) rowptr[0] = 0;
}

__global__ void k_init_cursor(const int* __restrict__ rowptr, int* __restrict__ cursor,
                              int* __restrict__ col, int n) {
    int i = blockIdx.x * blockDim.x + threadIdx.x;
    if (i < n) {
        int p = rowptr[i];
        col[p] = i;           // self loop first
        cursor[i] = p + 1;
    }
}

__global__ void k_scatter(const int* __restrict__ ei, int e, int* __restrict__ cursor,
                          int* __restrict__ col) {
    int i = blockIdx.x * blockDim.x + threadIdx.x;
    if (i < e) {
        int s = ei[i];
        int d = ei[e + i];
        int p = atomicAdd(&cursor[d], 1);
        col[p] = s;
    }
}

// ---------------- 3xTF32 tensor-core GEMM: C[M,BN] = A[M,K] @ B[K,BN] ----------
// Split a = hi + lo with hi = tf32(a); compute AhiBhi + AhiBlo + AloBhi in fp32
// accumulators -> fp32-accurate result on tensor cores.
__device__ __forceinline__ void split_tf32(float v, float& hi, float& lo) {
    hi = wmma::__float_to_tf32(v);
    lo = wmma::__float_to_tf32(v - hi);
}

template <int BN>
__global__ void __launch_bounds__(256) k_tf32gemm(const float* __restrict__ A,
                                                  const float* __restrict__ B,
                                                  float* __restrict__ C, int M, int K) {
    constexpr int BM = 128, BK = 16;
    constexpr int PA = BK + 4;   // 20 floats: row stride 80B (16B aligned)
    constexpr int PB = BN + 4;
    constexpr int WM = (BN == 128) ? 2 : 1;  // 16-row m-tiles per warp
    constexpr int WN = 4;                    // 16-col n-tiles per warp

    __shared__ float As_hi[BM][PA];
    __shared__ float As_lo[BM][PA];
    __shared__ float Bs_hi[BK][PB];
    __shared__ float Bs_lo[BK][PB];

    int tid = threadIdx.x;
    int wid = tid >> 5;
    int warp_m = (BN == 128) ? (wid >> 1) : wid;  // row group
    int warp_n = (BN == 128) ? (wid & 1) : 0;     // col group (64 cols)
    int blockRow = blockIdx.x * BM;

    wmma::fragment<wmma::accumulator, 16, 16, 8, float> acc[WM][WN];
#pragma unroll
    for (int m = 0; m < WM; m++)
#pragma unroll
        for (int n = 0; n < WN; n++) wmma::fill_fragment(acc[m][n], 0.0f);

    for (int k0 = 0; k0 < K; k0 += BK) {
        // ---- load + split A tile (128x16): 512 float4 over 256 threads ----
#pragma unroll
        for (int l = 0; l < 2; l++) {
            int f = tid + l * 256;
            int row = f >> 2, c4 = (f & 3) * 4;
            float4 v = make_float4(0.f, 0.f, 0.f, 0.f);
            int gr = blockRow + row;
            if (gr < M) v = *reinterpret_cast<const float4*>(&A[(size_t)gr * K + k0 + c4]);
            float4 h4, l4;
            split_tf32(v.x, h4.x, l4.x);
            split_tf32(v.y, h4.y, l4.y);
            split_tf32(v.z, h4.z, l4.z);
            split_tf32(v.w, h4.w, l4.w);
            *reinterpret_cast<float4*>(&As_hi[row][c4]) = h4;
            *reinterpret_cast<float4*>(&As_lo[row][c4]) = l4;
        }
        // ---- load + split B tile (16xBN) ----
        constexpr int BF4 = BK * BN / 4;
        constexpr int F4R = BN / 4;
#pragma unroll
        for (int l = 0; l < BF4 / 256; l++) {
            int f = tid + l * 256;
            int kr = f / F4R, c4 = (f % F4R) * 4;
            float4 v = *reinterpret_cast<const float4*>(&B[(size_t)(k0 + kr) * BN + c4]);
            float4 h4, l4;
            split_tf32(v.x, h4.x, l4.x);
            split_tf32(v.y, h4.y, l4.y);
            split_tf32(v.z, h4.z, l4.z);
            split_tf32(v.w, h4.w, l4.w);
            Bs_hi[kr][c4 + 0] = h4.x; Bs_hi[kr][c4 + 1] = h4.y;
            Bs_hi[kr][c4 + 2] = h4.z; Bs_hi[kr][c4 + 3] = h4.w;
            Bs_lo[kr][c4 + 0] = l4.x; Bs_lo[kr][c4 + 1] = l4.y;
            Bs_lo[kr][c4 + 2] = l4.z; Bs_lo[kr][c4 + 3] = l4.w;
        }
        __syncthreads();

#pragma unroll
        for (int kk = 0; kk < BK; kk += 8) {
            wmma::fragment<wmma::matrix_a, 16, 16, 8, wmma::precision::tf32, wmma::row_major> ah[WM], al[WM];
            wmma::fragment<wmma::matrix_b, 16, 16, 8, wmma::precision::tf32, wmma::row_major> bh[WN], bl[WN];
#pragma unroll
            for (int m = 0; m < WM; m++) {
                int r = (warp_m * WM + m) * 16;
                wmma::load_matrix_sync(ah[m], &As_hi[r][kk], PA);
                wmma::load_matrix_sync(al[m], &As_lo[r][kk], PA);
            }
#pragma unroll
            for (int n = 0; n < WN; n++) {
                int c = (warp_n * WN + n) * 16;
                wmma::load_matrix_sync(bh[n], &Bs_hi[kk][c], PB);
                wmma::load_matrix_sync(bl[n], &Bs_lo[kk][c], PB);
            }
#pragma unroll
            for (int m = 0; m < WM; m++)
#pragma unroll
                for (int n = 0; n < WN; n++) {
                    wmma::mma_sync(acc[m][n], ah[m], bl[n], acc[m][n]);
                    wmma::mma_sync(acc[m][n], al[m], bh[n], acc[m][n]);
                    wmma::mma_sync(acc[m][n], ah[m], bh[n], acc[m][n]);
                }
        }
        __syncthreads();
    }

    // ---- store (tile-granular row guard; M=50000 is a multiple of 16) ----
#pragma unroll
    for (int m = 0; m < WM; m++) {
        int r = blockRow + (warp_m * WM + m) * 16;
        if (r + 16 <= M) {
#pragma unroll
            for (int n = 0; n < WN; n++) {
                int c = (warp_n * WN + n) * 16;
                wmma::store_matrix_sync(&C[(size_t)r * BN + c], acc[m][n], BN, wmma::mem_row_major);
            }
        }
    }
}

// ---------------- bias + relu (for MLP heads) ----------------
__global__ void k_bias_relu(float* __restrict__ C, const float* __restrict__ bias, int total) {
    int i = blockIdx.x * blockDim.x + threadIdx.x;
    if (i * 4 < total) {
        float4 v = *reinterpret_cast<float4*>(&C[i * 4]);
        int c = (i * 4) & 63;
        v.x = fmaxf(v.x + bias[c + 0], 0.f);
        v.y = fmaxf(v.y + bias[c + 1], 0.f);
        v.z = fmaxf(v.z + bias[c + 2], 0.f);
        v.w = fmaxf(v.w + bias[c + 3], 0.f);
        *reinterpret_cast<float4*>(&C[i * 4]) = v;
    }
}

// ---------------- per-node attention score projections ----------------
template <int H>
__global__ void k_st(const float* __restrict__ h, const float* __restrict__ a_src,
                     const float* __restrict__ a_dst, float* __restrict__ s,
                     float* __restrict__ t, int n) {
    int g = blockIdx.x * blockDim.x + threadIdx.x;
    int w = g >> 5, lane = g & 31;
    if (w >= n * H) return;
    int node = w / H, head = w % H;
    const float* hp = h + (size_t)node * (H * 64) + head * 64;
    float v0 = hp[lane], v1 = hp[lane + 32];
    float as = v0 * a_src[head * 64 + lane] + v1 * a_src[head * 64 + lane + 32];
    float ad = v0 * a_dst[head * 64 + lane] + v1 * a_dst[head * 64 + lane + 32];
#pragma unroll
    for (int off = 16; off; off >>= 1) {
        as += __shfl_xor_sync(0xFFFFFFFFu, as, off);
        ad += __shfl_xor_sync(0xFFFFFFFFu, ad, off);
    }
    if (lane == 0) {
        s[w] = as;
        t[w] = ad;
    }
}

// ---------------- GAT aggregation: one block per dst node ----------------
template <int H, bool RELU>
__global__ void __launch_bounds__(H * 64) k_agg(const float* __restrict__ hin,
                                                const float* __restrict__ s,
                                                const float* __restrict__ t,
                                                const int* __restrict__ rowptr,
                                                const int* __restrict__ col,
                                                const float* __restrict__ bias,
                                                float* __restrict__ out) {
    constexpr int W = H * 64;
    constexpr int CH = 128;
    __shared__ float sh_m[H];
    __shared__ float sh_inv[H];
    __shared__ float red[W / 32];
    __shared__ int sh_src[CH];
    __shared__ float sh_al[CH * H];

    int node = blockIdx.x;
    int tid = threadIdx.x;
    int lane = tid & 31, warp = tid >> 5;
    int start = rowptr[node];
    int deg = rowptr[node + 1] - start;

    float tn[H];
#pragma unroll
    for (int h = 0; h < H; h++) tn[h] = t[node * H + h];

    // ---- pass 1: segment max per head ----
    float mx[H];
#pragma unroll
    for (int h = 0; h < H; h++) mx[h] = -1e30f;
    for (int k = tid; k < deg; k += W) {
        int src = col[start + k];
#pragma unroll
        for (int h = 0; h < H; h++) {
            float e = s[src * H + h] + tn[h];
            e = e > 0.f ? e : NEG_SLOPE * e;
            mx[h] = fmaxf(mx[h], e);
        }
    }
#pragma unroll
    for (int h = 0; h < H; h++) {
        float v = mx[h];
#pragma unroll
        for (int off = 16; off; off >>= 1) v = fmaxf(v, __shfl_xor_sync(0xFFFFFFFFu, v, off));
        if (lane == 0) red[warp] = v;
        __syncthreads();
        if (tid == 0) {
            float r = red[0];
            for (int w = 1; w < W / 32; w++) r = fmaxf(r, red[w]);
            sh_m[h] = r;
        }
        __syncthreads();
    }

    // ---- pass 2: sum of exp ----
    float sum[H];
#pragma unroll
    for (int h = 0; h < H; h++) sum[h] = 0.f;
    for (int k = tid; k < deg; k += W) {
        int src = col[start + k];
#pragma unroll
        for (int h = 0; h < H; h++) {
            float e = s[src * H + h] + tn[h];
            e = e > 0.f ? e : NEG_SLOPE * e;
            sum[h] += __expf(e - sh_m[h]);
        }
    }
#pragma unroll
    for (int h = 0; h < H; h++) {
        float v = sum[h];
#pragma unroll
        for (int off = 16; off; off >>= 1) v += __shfl_xor_sync(0xFFFFFFFFu, v, off);
        if (lane == 0) red[warp] = v;
        __syncthreads();
        if (tid == 0) {
            float r = red[0];
            for (int w = 1; w < W / 32; w++) r += red[w];
            sh_inv[h] = 1.f / (r + 1e-16f);
        }
        __syncthreads();
    }

    // ---- pass 3: weighted gather-sum, chunked through shared ----
    float acc = 0.f;
    int myhead = (H == 2) ? (tid >> 6) : 0;
    for (int base = 0; base < deg; base += CH) {
        int nk = min(CH, deg - base);
        for (int k = tid; k < nk * H; k += W) {
            int e_idx = (H == 2) ? (k >> 1) : k;
            int hh = (H == 2) ? (k & 1) : 0;
            int src = col[start + base + e_idx];
            float e = s[src * H + hh] + tn[hh];
            e = e > 0.f ? e : NEG_SLOPE * e;
            sh_al[e_idx * H + hh] = __expf(e - sh_m[hh]) * sh_inv[hh];
            if (hh == 0) sh_src[e_idx] = src;
        }
        __syncthreads();
#pragma unroll 4
        for (int e2 = 0; e2 < nk; e2++) {
            acc += hin[(size_t)sh_src[e2] * W + tid] * sh_al[e2 * H + myhead];
        }
        __syncthreads();
    }

    float v = acc + bias[tid];
    if (RELU) v = fmaxf(v, 0.f);
    out[(size_t)node * W + tid] = v;
}

// ---------------- host launch ----------------
extern "C" void kernel_launch(void* const* d_in, const int* in_sizes, int n_in,
                              void* d_out, int out_size) {
    const float* x     = (const float*)d_in[0];
    const int*   ei    = (const int*)d_in[1];
    const float* W0    = (const float*)d_in[2];
    const float* as0   = (const float*)d_in[3];
    const float* ad0   = (const float*)d_in[4];
    const float* b0    = (const float*)d_in[5];
    const float* W1    = (const float*)d_in[6];
    const float* as1   = (const float*)d_in[7];
    const float* ad1   = (const float*)d_in[8];
    const float* b1    = (const float*)d_in[9];
    const float* W2    = (const float*)d_in[10];
    const float* as2   = (const float*)d_in[11];
    const float* ad2   = (const float*)d_in[12];
    const float* b2    = (const float*)d_in[13];
    const float* Wv    = (const float*)d_in[14];
    const float* bv    = (const float*)d_in[15];
    const float* Wt    = (const float*)d_in[16];
    const float* bt    = (const float*)d_in[17];

    int N = in_sizes[0] / 512;
    int E = in_sizes[1] / 2;

    float* out = (float*)d_out;
    float* h_out = out;
    float* vis = out + (size_t)N * 64;
    float* txt = out + (size_t)N * 64 * 2;

    float *h0, *h1, *sA, *tA;
    int *deg, *rowptr, *cursor, *colA;
    cudaGetSymbolAddress((void**)&h0, g_h0);
    cudaGetSymbolAddress((void**)&h1, g_h1);
    cudaGetSymbolAddress((void**)&sA, g_s);
    cudaGetSymbolAddress((void**)&tA, g_t);
    cudaGetSymbolAddress((void**)&deg, g_deg);
    cudaGetSymbolAddress((void**)&rowptr, g_rowptr);
    cudaGetSymbolAddress((void**)&cursor, g_cursor);
    cudaGetSymbolAddress((void**)&colA, g_col);

    // ---- CSR build (dst-major, self loop first in each row) ----
    k_init_deg<<<(N + 255) / 256, 256>>>(deg, N);
    k_hist<<<(E + 255) / 256, 256>>>(ei, E, deg);
    k_scan<<<1, 1024>>>(deg, rowptr, N);
    k_init_cursor<<<(N + 255) / 256, 256>>>(rowptr, cursor, colA, N);
    k_scatter<<<(E + 255) / 256, 256>>>(ei, E, cursor, colA);

    int gblk = (N + 127) / 128;

    // ---- layer 0: 512 -> 2x64 ----
    k_tf32gemm<128><<<gblk, 256>>>(x, W0, h0, N, 512);
    k_st<2><<<(N * 2 * 32 + 255) / 256, 256>>>(h0, as0, ad0, sA, tA, N);
    k_agg<2, true><<<N, 128>>>(h0, sA, tA, rowptr, colA, b0, h1);

    // ---- layer 1: 128 -> 2x64 ----
    k_tf32gemm<128><<<gblk, 256>>>(h1, W1, h0, N, 128);
    k_st<2><<<(N * 2 * 32 + 255) / 256, 256>>>(h0, as1, ad1, sA, tA, N);
    k_agg<2, true><<<N, 128>>>(h0, sA, tA, rowptr, colA, b1, h1);

    // ---- layer 2: 128 -> 64 (heads=1, no relu) ----
    k_tf32gemm<64><<<gblk, 256>>>(h1, W2, h0, N, 128);
    k_st<1><<<(N * 32 + 255) / 256, 256>>>(h0, as2, ad2, sA, tA, N);
    k_agg<1, false><<<N, 64>>>(h0, sA, tA, rowptr, colA, b2, h_out);

    // ---- MLP heads ----
    k_tf32gemm<64><<<gblk, 256>>>(h_out, Wv, vis, N, 64);
    k_bias_relu<<<(N * 64 / 4 + 255) / 256, 256>>>(vis, bv, N * 64);
    k_tf32gemm<64><<<gblk, 256>>>(h_out, Wt, txt, N, 64);
    k_bias_relu<<<(N * 64 / 4 + 255) / 256, 256>>>(txt, bt, N * 64);
}

// round 4
// speedup vs baseline: 1.4836x; 1.4836x over previous
#include <cuda_runtime.h>
#include <cstdint>

#define NNODES 50000
#define NEDGES 800000
#define TOTEDGES (NEDGES + NNODES)
#define NEG_SLOPE 0.2f

// ---------------- scratch (allocation-free: device globals) ----------------
__device__ float g_h0[(size_t)NNODES * 128];
__device__ float g_h1[(size_t)NNODES * 128];
__device__ float g_s[NNODES * 2];
__device__ float g_t[NNODES * 2];
__device__ int   g_deg[NNODES];
__device__ int   g_rowptr[NNODES + 1];
__device__ int   g_cursor[NNODES];
__device__ int   g_col[TOTEDGES];
__device__ float g_Wcat[64 * 128];
__device__ float g_bcat[128];

// ---------------- helpers ----------------
__device__ __forceinline__ uint32_t smem_u32(const void* p) {
    return (uint32_t)__cvta_generic_to_shared(p);
}
typedef unsigned long long ull;
__device__ __forceinline__ ull pk2(float x, float y) {
    ull r;
    asm("mov.b64 %0, {%1, %2};" : "=l"(r) : "f"(x), "f"(y));
    return r;
}
__device__ __forceinline__ ull splat2(float x) {
    ull r;
    asm("mov.b64 %0, {%1, %1};" : "=l"(r) : "f"(x));
    return r;
}
__device__ __forceinline__ void fma2(ull& d, ull a, ull b) {
    asm("fma.rn.f32x2 %0, %1, %2, %3;" : "=l"(d) : "l"(a), "l"(b), "l"(d));
}
__device__ __forceinline__ void upk2(ull v, float& lo, float& hi) {
    asm("mov.b64 {%0, %1}, %2;" : "=f"(lo), "=f"(hi) : "l"(v));
}
__device__ __forceinline__ void cpa16(uint32_t dst, const void* src) {
    asm volatile("cp.async.cg.shared.global [%0], [%1], 16;" :: "r"(dst), "l"(src));
}

// ---------------- CSR build ----------------
__global__ void k_init_deg(int* __restrict__ deg, int n) {
    int i = blockIdx.x * blockDim.x + threadIdx.x;
    if (i < n) deg[i] = 1;
}
__global__ void k_hist(const int* __restrict__ ei, int e, int* __restrict__ deg) {
    int i = blockIdx.x * blockDim.x + threadIdx.x;
    if (i < e) atomicAdd(&deg[ei[e + i]], 1);
}
__global__ void k_scan(const int* __restrict__ deg, int* __restrict__ rowptr, int n) {
    __shared__ int wsum[32];
    __shared__ int s_run;
    int tid = threadIdx.x, lane = tid & 31, w = tid >> 5;
    if (tid == 0) s_run = 0;
    __syncthreads();
    for (int base = 0; base < n; base += 1024) {
        int v = (base + tid < n) ? deg[base + tid] : 0;
        int x = v;
#pragma unroll
        for (int off = 1; off < 32; off <<= 1) {
            int y = __shfl_up_sync(0xFFFFFFFFu, x, off);
            if (lane >= off) x += y;
        }
        if (lane == 31) wsum[w] = x;
        __syncthreads();
        if (w == 0) {
            int sv = wsum[lane];
#pragma unroll
            for (int off = 1; off < 32; off <<= 1) {
                int y = __shfl_up_sync(0xFFFFFFFFu, sv, off);
                if (lane >= off) sv += y;
            }
            wsum[lane] = sv;
        }
        __syncthreads();
        int woff = (w > 0) ? wsum[w - 1] : 0;
        if (base + tid < n) rowptr[base + tid + 1] = x + woff + s_run;
        __syncthreads();
        if (tid == 0) s_run += wsum[31];
        __syncthreads();
    }
    if (tid == 0) rowptr[0] = 0;
}
__global__ void k_init_cursor(const int* __restrict__ rowptr, int* __restrict__ cursor,
                              int* __restrict__ col, int n) {
    int i = blockIdx.x * blockDim.x + threadIdx.x;
    if (i < n) {
        int p = rowptr[i];
        col[p] = i;
        cursor[i] = p + 1;
    }
}
__global__ void k_scatter(const int* __restrict__ ei, int e, int* __restrict__ cursor,
                          int* __restrict__ col) {
    int i = blockIdx.x * blockDim.x + threadIdx.x;
    if (i < e) {
        int s = ei[i];
        int d = ei[e + i];
        int p = atomicAdd(&cursor[d], 1);
        col[p] = s;
    }
}

// ---------------- Wcat prep ----------------
__global__ void k_prep(const float* __restrict__ Wv, const float* __restrict__ bv,
                       const float* __restrict__ Wt, const float* __restrict__ bt,
                       float* __restrict__ Wcat, float* __restrict__ bcat) {
    int i = blockIdx.x * blockDim.x + threadIdx.x;
    if (i < 64 * 128) {
        int k = i >> 7, n = i & 127;
        Wcat[i] = (n < 64) ? Wv[k * 64 + n] : Wt[k * 64 + (n - 64)];
    }
    if (i < 128) bcat[i] = (i < 64) ? bv[i] : bt[i - 64];
}

// ---------------- f32x2 GEMM: C[M,BN] = A[M,K] @ B[K,BN] ----------------
// cp.async double-buffered. Optional fused outputs:
//  - s_out/t_out: per-row attention projections (dot with a_src/a_dst)
//  - C2: split-store mode (cols 0-63 -> C, 64-127 -> C2, both stride 64)
template <int BN>
__global__ void __launch_bounds__(256) k_gemm(
    const float* __restrict__ A, const float* __restrict__ B,
    float* __restrict__ C, float* __restrict__ C2, int M, int K,
    const float* __restrict__ bias, int relu,
    const float* __restrict__ a_src, const float* __restrict__ a_dst,
    float* __restrict__ s_out, float* __restrict__ t_out)
{
    constexpr int BM = 128, BK = 16, TN = BN / 16;
    __shared__ float As[2][BM][BK];
    __shared__ float Bs[2][BK][BN];
    __shared__ float sh_att[2 * BN];  // a_src | a_dst (flat, head-major)

    int tid = threadIdx.x;
    int tx = tid & 15, ty = tid >> 4;
    int blockRow = blockIdx.x * BM;

    if (a_src) {
        if (tid < BN) sh_att[tid] = a_src[tid];
        else if (tid < 2 * BN) sh_att[tid] = a_dst[tid - BN];
    }

    ull acc[8][TN / 2];
#pragma unroll
    for (int i = 0; i < 8; i++)
#pragma unroll
        for (int j = 0; j < TN / 2; j++) acc[i][j] = 0ull;

    int nch = K / BK;

    // stage loaders
    auto loadA = [&](int c, int st) {
        int k0 = c * BK;
#pragma unroll
        for (int l = 0; l < 2; l++) {
            int f = tid + l * 256;
            int row = f >> 2, q = f & 3;
            int gr = blockRow + row;
            if (gr >= M) gr = M - 1;
            cpa16(smem_u32(&As[st][row][q * 4]), &A[(size_t)gr * K + k0 + q * 4]);
        }
    };
    auto loadB = [&](int c, int st) {
        int k0 = c * BK;
        constexpr int CH = BK * BN / 4;
#pragma unroll
        for (int l = 0; l < CH / 256; l++) {
            int f = tid + l * 256;
            int kr = f / (BN / 4), q = f % (BN / 4);
            cpa16(smem_u32(&Bs[st][kr][q * 4]), &B[(size_t)(k0 + kr) * BN + q * 4]);
        }
    };

    loadA(0, 0);
    loadB(0, 0);
    asm volatile("cp.async.commit_group;");

    for (int c = 0; c < nch; c++) {
        int st = c & 1;
        if (c + 1 < nch) {
            loadA(c + 1, (c + 1) & 1);
            loadB(c + 1, (c + 1) & 1);
            asm volatile("cp.async.commit_group;");
            asm volatile("cp.async.wait_group 1;");
        } else {
            asm volatile("cp.async.wait_group 0;");
        }
        __syncthreads();

#pragma unroll
        for (int k4 = 0; k4 < BK; k4 += 4) {
            float4 a4[8];
#pragma unroll
            for (int i = 0; i < 8; i++)
                a4[i] = *reinterpret_cast<const float4*>(&As[st][ty * 8 + i][k4]);
#pragma unroll
            for (int kk = 0; kk < 4; kk++) {
                ull b2[TN / 2];
                {
                    float4 bv0 = *reinterpret_cast<const float4*>(&Bs[st][k4 + kk][tx * TN]);
                    b2[0] = pk2(bv0.x, bv0.y);
                    b2[1] = pk2(bv0.z, bv0.w);
                    if (TN == 8) {
                        float4 bv1 = *reinterpret_cast<const float4*>(&Bs[st][k4 + kk][tx * TN + 4]);
                        b2[2] = pk2(bv1.x, bv1.y);
                        b2[3] = pk2(bv1.z, bv1.w);
                    }
                }
#pragma unroll
                for (int i = 0; i < 8; i++) {
                    float av = (kk == 0) ? a4[i].x : (kk == 1) ? a4[i].y : (kk == 2) ? a4[i].z : a4[i].w;
                    ull a2 = splat2(av);
#pragma unroll
                    for (int j = 0; j < TN / 2; j++) fma2(acc[i][j], a2, b2[j]);
                }
            }
        }
        __syncthreads();
    }

    // ---- unpack ----
    float accf[8][TN];
#pragma unroll
    for (int i = 0; i < 8; i++)
#pragma unroll
        for (int j = 0; j < TN / 2; j++) upk2(acc[i][j], accf[i][2 * j], accf[i][2 * j + 1]);

    // ---- fused s/t projections ----
    if (s_out) {
#pragma unroll
        for (int i = 0; i < 8; i++) {
            float ps = 0.f, pt = 0.f;
#pragma unroll
            for (int j = 0; j < TN; j++) {
                int col = tx * TN + j;
                ps += accf[i][j] * sh_att[col];
                pt += accf[i][j] * sh_att[BN + col];
            }
            if (BN == 128) {
                // reduce over 8-lane tx groups (one head each)
#pragma unroll
                for (int off = 4; off; off >>= 1) {
                    ps += __shfl_xor_sync(0xFFFFFFFFu, ps, off);
                    pt += __shfl_xor_sync(0xFFFFFFFFu, pt, off);
                }
                if ((tx & 7) == 0) {
                    int head = tx >> 3;
                    int r = blockRow + ty * 8 + i;
                    if (r < M) {
                        s_out[r * 2 + head] = ps;
                        t_out[r * 2 + head] = pt;
                    }
                }
            } else {
                // reduce over 16-lane groups (single head)
#pragma unroll
                for (int off = 8; off; off >>= 1) {
                    ps += __shfl_xor_sync(0xFFFFFFFFu, ps, off);
                    pt += __shfl_xor_sync(0xFFFFFFFFu, pt, off);
                }
                if (tx == 0) {
                    int r = blockRow + ty * 8 + i;
                    if (r < M) {
                        s_out[r] = ps;
                        t_out[r] = pt;
                    }
                }
            }
        }
    }

    // ---- store ----
#pragma unroll
    for (int i = 0; i < 8; i++) {
        int r = blockRow + ty * 8 + i;
        if (r >= M) continue;
#pragma unroll
        for (int j4 = 0; j4 < TN / 4; j4++) {
            int col = tx * TN + j4 * 4;
            float4 v;
            v.x = accf[i][j4 * 4 + 0];
            v.y = accf[i][j4 * 4 + 1];
            v.z = accf[i][j4 * 4 + 2];
            v.w = accf[i][j4 * 4 + 3];
            if (bias) {
                v.x += bias[col + 0]; v.y += bias[col + 1];
                v.z += bias[col + 2]; v.w += bias[col + 3];
            }
            if (relu) {
                v.x = fmaxf(v.x, 0.f); v.y = fmaxf(v.y, 0.f);
                v.z = fmaxf(v.z, 0.f); v.w = fmaxf(v.w, 0.f);
            }
            if (C2) {  // split mode (BN=128): cols 0-63 -> C, 64-127 -> C2
                float* dst = (col < 64) ? C : C2;
                *reinterpret_cast<float4*>(&dst[(size_t)r * 64 + (col & 63)]) = v;
            } else {
                *reinterpret_cast<float4*>(&C[(size_t)r * BN + col]) = v;
            }
        }
    }
}

// ---------------- GAT aggregation: one block per dst node ----------------
template <int H, bool RELU>
__global__ void __launch_bounds__(H * 64) k_agg(const float* __restrict__ hin,
                                                const float* __restrict__ s,
                                                const float* __restrict__ t,
                                                const int* __restrict__ rowptr,
                                                const int* __restrict__ col,
                                                const float* __restrict__ bias,
                                                float* __restrict__ out) {
    constexpr int W = H * 64;
    constexpr int CH = 128;
    __shared__ float sh_m[H];
    __shared__ float sh_inv[H];
    __shared__ float red[W / 32];
    __shared__ int sh_src[CH];
    __shared__ float sh_al[CH * H];

    int node = blockIdx.x;
    int tid = threadIdx.x;
    int lane = tid & 31, warp = tid >> 5;
    int start = rowptr[node];
    int deg = rowptr[node + 1] - start;

    float tn[H];
#pragma unroll
    for (int h = 0; h < H; h++) tn[h] = t[node * H + h];

    float mx[H];
#pragma unroll
    for (int h = 0; h < H; h++) mx[h] = -1e30f;
    for (int k = tid; k < deg; k += W) {
        int src = col[start + k];
#pragma unroll
        for (int h = 0; h < H; h++) {
            float e = s[src * H + h] + tn[h];
            e = e > 0.f ? e : NEG_SLOPE * e;
            mx[h] = fmaxf(mx[h], e);
        }
    }
#pragma unroll
    for (int h = 0; h < H; h++) {
        float v = mx[h];
#pragma unroll
        for (int off = 16; off; off >>= 1) v = fmaxf(v, __shfl_xor_sync(0xFFFFFFFFu, v, off));
        if (lane == 0) red[warp] = v;
        __syncthreads();
        if (tid == 0) {
            float r = red[0];
            for (int w = 1; w < W / 32; w++) r = fmaxf(r, red[w]);
            sh_m[h] = r;
        }
        __syncthreads();
    }

    float sum[H];
#pragma unroll
    for (int h = 0; h < H; h++) sum[h] = 0.f;
    for (int k = tid; k < deg; k += W) {
        int src = col[start + k];
#pragma unroll
        for (int h = 0; h < H; h++) {
            float e = s[src * H + h] + tn[h];
            e = e > 0.f ? e : NEG_SLOPE * e;
            sum[h] += __expf(e - sh_m[h]);
        }
    }
#pragma unroll
    for (int h = 0; h < H; h++) {
        float v = sum[h];
#pragma unroll
        for (int off = 16; off; off >>= 1) v += __shfl_xor_sync(0xFFFFFFFFu, v, off);
        if (lane == 0) red[warp] = v;
        __syncthreads();
        if (tid == 0) {
            float r = red[0];
            for (int w = 1; w < W / 32; w++) r += red[w];
            sh_inv[h] = 1.f / (r + 1e-16f);
        }
        __syncthreads();
    }

    float acc = 0.f;
    int myhead = (H == 2) ? (tid >> 6) : 0;
    for (int base = 0; base < deg; base += CH) {
        int nk = min(CH, deg - base);
        for (int k = tid; k < nk * H; k += W) {
            int e_idx = (H == 2) ? (k >> 1) : k;
            int hh = (H == 2) ? (k & 1) : 0;
            int src = col[start + base + e_idx];
            float e = s[src * H + hh] + tn[hh];
            e = e > 0.f ? e : NEG_SLOPE * e;
            sh_al[e_idx * H + hh] = __expf(e - sh_m[hh]) * sh_inv[hh];
            if (hh == 0) sh_src[e_idx] = src;
        }
        __syncthreads();
#pragma unroll 4
        for (int e2 = 0; e2 < nk; e2++) {
            acc += hin[(size_t)sh_src[e2] * W + tid] * sh_al[e2 * H + myhead];
        }
        __syncthreads();
    }

    float v = acc + bias[tid];
    if (RELU) v = fmaxf(v, 0.f);
    out[(size_t)node * W + tid] = v;
}

// ---------------- host launch ----------------
extern "C" void kernel_launch(void* const* d_in, const int* in_sizes, int n_in,
                              void* d_out, int out_size) {
    const float* x     = (const float*)d_in[0];
    const int*   ei    = (const int*)d_in[1];
    const float* W0    = (const float*)d_in[2];
    const float* as0   = (const float*)d_in[3];
    const float* ad0   = (const float*)d_in[4];
    const float* b0    = (const float*)d_in[5];
    const float* W1    = (const float*)d_in[6];
    const float* as1   = (const float*)d_in[7];
    const float* ad1   = (const float*)d_in[8];
    const float* b1    = (const float*)d_in[9];
    const float* W2    = (const float*)d_in[10];
    const float* as2   = (const float*)d_in[11];
    const float* ad2   = (const float*)d_in[12];
    const float* b2    = (const float*)d_in[13];
    const float* Wv    = (const float*)d_in[14];
    const float* bv    = (const float*)d_in[15];
    const float* Wt    = (const float*)d_in[16];
    const float* bt    = (const float*)d_in[17];

    int N = in_sizes[0] / 512;
    int E = in_sizes[1] / 2;

    float* out = (float*)d_out;
    float* h_out = out;
    float* vis = out + (size_t)N * 64;
    float* txt = out + (size_t)N * 64 * 2;

    float *h0, *h1, *sA, *tA, *Wcat, *bcat;
    int *deg, *rowptr, *cursor, *colA;
    cudaGetSymbolAddress((void**)&h0, g_h0);
    cudaGetSymbolAddress((void**)&h1, g_h1);
    cudaGetSymbolAddress((void**)&sA, g_s);
    cudaGetSymbolAddress((void**)&tA, g_t);
    cudaGetSymbolAddress((void**)&deg, g_deg);
    cudaGetSymbolAddress((void**)&rowptr, g_rowptr);
    cudaGetSymbolAddress((void**)&cursor, g_cursor);
    cudaGetSymbolAddress((void**)&colA, g_col);
    cudaGetSymbolAddress((void**)&Wcat, g_Wcat);
    cudaGetSymbolAddress((void**)&bcat, g_bcat);

    // ---- CSR build (launches 0-4) ----
    k_init_deg<<<(N + 255) / 256, 256>>>(deg, N);
    k_hist<<<(E + 255) / 256, 256>>>(ei, E, deg);
    k_scan<<<1, 1024>>>(deg, rowptr, N);
    k_init_cursor<<<(N + 255) / 256, 256>>>(rowptr, cursor, colA, N);
    k_scatter<<<(E + 255) / 256, 256>>>(ei, E, cursor, colA);

    int gblk = (N + 127) / 128;

    // ---- layer 0: 512 -> 2x64 (launch 5: ncu target) ----
    k_gemm<128><<<gblk, 256>>>(x, W0, h0, nullptr, N, 512, nullptr, 0, as0, ad0, sA, tA);
    k_agg<2, true><<<N, 128>>>(h0, sA, tA, rowptr, colA, b0, h1);

    // ---- layer 1: 128 -> 2x64 ----
    k_gemm<128><<<gblk, 256>>>(h1, W1, h0, nullptr, N, 128, nullptr, 0, as1, ad1, sA, tA);
    k_agg<2, true><<<N, 128>>>(h0, sA, tA, rowptr, colA, b1, h1);

    // ---- layer 2: 128 -> 64 (heads=1, no relu) ----
    k_gemm<64><<<gblk, 256>>>(h1, W2, h0, nullptr, N, 128, nullptr, 0, as2, ad2, sA, tA);
    k_agg<1, false><<<N, 64>>>(h0, sA, tA, rowptr, colA, b2, h_out);

    // ---- MLP heads: one combined GEMM with split store ----
    k_prep<<<(64 * 128 + 255) / 256, 256>>>(Wv, bv, Wt, bt, Wcat, bcat);
    k_gemm<128><<<gblk, 256>>>(h_out, Wcat, vis, txt, N, 64, bcat, 1,
                               nullptr, nullptr, nullptr, nullptr);
}

// round 5
// speedup vs baseline: 1.9684x; 1.3268x over previous
#include <cuda_runtime.h>
#include <cstdint>

#define NNODES 50000
#define NEDGES 800000
#define TOTEDGES (NEDGES + NNODES)
#define NEG_SLOPE 0.2f

// ---------------- scratch (allocation-free: device globals) ----------------
__device__ float g_h0[(size_t)NNODES * 128];
__device__ float g_h1[(size_t)NNODES * 128];
__device__ float g_s[NNODES * 2];
__device__ float g_t[NNODES * 2];
__device__ int   g_deg[NNODES];
__device__ int   g_rowptr[NNODES + 1];
__device__ int   g_cursor[NNODES];
__device__ int   g_col[TOTEDGES];
__device__ int   g_bsum[256];
__device__ int   g_bexc[256];
__device__ float g_Wcat[64 * 128];
__device__ float g_bcat[128];

// ---------------- helpers ----------------
__device__ __forceinline__ uint32_t smem_u32(const void* p) {
    return (uint32_t)__cvta_generic_to_shared(p);
}
typedef unsigned long long ull;
__device__ __forceinline__ ull pk2(float x, float y) {
    ull r;
    asm("mov.b64 %0, {%1, %2};" : "=l"(r) : "f"(x), "f"(y));
    return r;
}
__device__ __forceinline__ ull splat2(float x) {
    ull r;
    asm("mov.b64 %0, {%1, %1};" : "=l"(r) : "f"(x));
    return r;
}
__device__ __forceinline__ void fma2(ull& d, ull a, ull b) {
    asm("fma.rn.f32x2 %0, %1, %2, %3;" : "=l"(d) : "l"(a), "l"(b), "l"(d));
}
__device__ __forceinline__ void upk2(ull v, float& lo, float& hi) {
    asm("mov.b64 {%0, %1}, %2;" : "=f"(lo), "=f"(hi) : "l"(v));
}
__device__ __forceinline__ void cpa16(uint32_t dst, const void* src) {
    asm volatile("cp.async.cg.shared.global [%0], [%1], 16;" :: "r"(dst), "l"(src));
}

// ---------------- CSR build ----------------
__global__ void k_init_deg(int* __restrict__ deg, int n) {
    int i = blockIdx.x * blockDim.x + threadIdx.x;
    if (i < n) deg[i] = 1;
}
__global__ void k_hist(const int* __restrict__ ei, int e, int* __restrict__ deg) {
    int i = blockIdx.x * blockDim.x + threadIdx.x;
    if (i < e) atomicAdd(&deg[ei[e + i]], 1);
}
// per-block sums of deg (256 per block)
__global__ void k_blocksums(const int* __restrict__ deg, int* __restrict__ bsum, int n) {
    __shared__ int wred[8];
    int i = blockIdx.x * 256 + threadIdx.x;
    int v = (i < n) ? deg[i] : 0;
    int lane = threadIdx.x & 31, w = threadIdx.x >> 5;
#pragma unroll
    for (int off = 16; off; off >>= 1) v += __shfl_xor_sync(0xFFFFFFFFu, v, off);
    if (lane == 0) wred[w] = v;
    __syncthreads();
    if (threadIdx.x == 0) {
        int s = 0;
#pragma unroll
        for (int k = 0; k < 8; k++) s += wred[k];
        bsum[blockIdx.x] = s;
    }
}
// exclusive scan over nb block sums (nb <= 256), one block
__global__ void k_scan_top(const int* __restrict__ bsum, int* __restrict__ bexc, int nb) {
    __shared__ int wred[8];
    int tid = threadIdx.x, lane = tid & 31, w = tid >> 5;
    int v = (tid < nb) ? bsum[tid] : 0;
    int x = v;
#pragma unroll
    for (int off = 1; off < 32; off <<= 1) {
        int y = __shfl_up_sync(0xFFFFFFFFu, x, off);
        if (lane >= off) x += y;
    }
    if (lane == 31) wred[w] = x;
    __syncthreads();
    if (w == 0) {
        int sv = (lane < 8) ? wred[lane] : 0;
#pragma unroll
        for (int off = 1; off < 8; off <<= 1) {
            int y = __shfl_up_sync(0xFFFFFFFFu, sv, off);
            if (lane >= off) sv += y;
        }
        if (lane < 8) wred[lane] = sv;
    }
    __syncthreads();
    int woff = (w > 0) ? wred[w - 1] : 0;
    if (tid < nb) bexc[tid] = x + woff - v;  // exclusive
}
// rescan chunk + apply offset; write rowptr, cursor, self-loop col
__global__ void k_scan_apply(const int* __restrict__ deg, const int* __restrict__ bexc,
                             int* __restrict__ rowptr, int* __restrict__ cursor,
                             int* __restrict__ col, int n) {
    __shared__ int wred[8];
    int i = blockIdx.x * 256 + threadIdx.x;
    int tid = threadIdx.x, lane = tid & 31, w = tid >> 5;
    int v = (i < n) ? deg[i] : 0;
    int x = v;
#pragma unroll
    for (int off = 1; off < 32; off <<= 1) {
        int y = __shfl_up_sync(0xFFFFFFFFu, x, off);
        if (lane >= off) x += y;
    }
    if (lane == 31) wred[w] = x;
    __syncthreads();
    if (w == 0) {
        int sv = (lane < 8) ? wred[lane] : 0;
#pragma unroll
        for (int off = 1; off < 8; off <<= 1) {
            int y = __shfl_up_sync(0xFFFFFFFFu, sv, off);
            if (lane >= off) sv += y;
        }
        if (lane < 8) wred[lane] = sv;
    }
    __syncthreads();
    int woff = (w > 0) ? wred[w - 1] : 0;
    if (i < n) {
        int incl = x + woff + bexc[blockIdx.x];
        rowptr[i + 1] = incl;
        int p = incl - v;        // exclusive start
        col[p] = i;              // self loop first
        cursor[i] = p + 1;
        if (i == 0) rowptr[0] = 0;
    }
}
__global__ void k_scatter(const int* __restrict__ ei, int e, int* __restrict__ cursor,
                          int* __restrict__ col) {
    int i = blockIdx.x * blockDim.x + threadIdx.x;
    if (i < e) {
        int s = ei[i];
        int d = ei[e + i];
        int p = atomicAdd(&cursor[d], 1);
        col[p] = s;
    }
}

// ---------------- Wcat prep ----------------
__global__ void k_prep(const float* __restrict__ Wv, const float* __restrict__ bv,
                       const float* __restrict__ Wt, const float* __restrict__ bt,
                       float* __restrict__ Wcat, float* __restrict__ bcat) {
    int i = blockIdx.x * blockDim.x + threadIdx.x;
    if (i < 64 * 128) {
        int k = i >> 7, n = i & 127;
        Wcat[i] = (n < 64) ? Wv[k * 64 + n] : Wt[k * 64 + (n - 64)];
    }
    if (i < 128) bcat[i] = (i < 64) ? bv[i] : bt[i - 64];
}

// ---------------- f32x2 GEMM: C[M,BN] = A[M,K] @ B[K,BN] ----------------
template <int BN>
__global__ void __launch_bounds__(256) k_gemm(
    const float* __restrict__ A, const float* __restrict__ B,
    float* __restrict__ C, float* __restrict__ C2, int M, int K,
    const float* __restrict__ bias, int relu,
    const float* __restrict__ a_src, const float* __restrict__ a_dst,
    float* __restrict__ s_out, float* __restrict__ t_out)
{
    constexpr int BM = 128, BK = 16, TN = BN / 16;
    __shared__ float As[2][BM][BK];
    __shared__ float Bs[2][BK][BN];
    __shared__ float sh_att[2 * BN];

    int tid = threadIdx.x;
    int tx = tid & 15, ty = tid >> 4;
    int blockRow = blockIdx.x * BM;

    if (a_src) {
        if (tid < BN) sh_att[tid] = a_src[tid];
        else if (tid < 2 * BN) sh_att[tid] = a_dst[tid - BN];
    }

    ull acc[8][TN / 2];
#pragma unroll
    for (int i = 0; i < 8; i++)
#pragma unroll
        for (int j = 0; j < TN / 2; j++) acc[i][j] = 0ull;

    int nch = K / BK;

    auto loadA = [&](int c, int st) {
        int k0 = c * BK;
#pragma unroll
        for (int l = 0; l < 2; l++) {
            int f = tid + l * 256;
            int row = f >> 2, q = f & 3;
            int gr = blockRow + row;
            if (gr >= M) gr = M - 1;
            cpa16(smem_u32(&As[st][row][q * 4]), &A[(size_t)gr * K + k0 + q * 4]);
        }
    };
    auto loadB = [&](int c, int st) {
        int k0 = c * BK;
        constexpr int CH = BK * BN / 4;
#pragma unroll
        for (int l = 0; l < CH / 256; l++) {
            int f = tid + l * 256;
            int kr = f / (BN / 4), q = f % (BN / 4);
            cpa16(smem_u32(&Bs[st][kr][q * 4]), &B[(size_t)(k0 + kr) * BN + q * 4]);
        }
    };

    loadA(0, 0);
    loadB(0, 0);
    asm volatile("cp.async.commit_group;");

    for (int c = 0; c < nch; c++) {
        int st = c & 1;
        if (c + 1 < nch) {
            loadA(c + 1, (c + 1) & 1);
            loadB(c + 1, (c + 1) & 1);
            asm volatile("cp.async.commit_group;");
            asm volatile("cp.async.wait_group 1;");
        } else {
            asm volatile("cp.async.wait_group 0;");
        }
        __syncthreads();

#pragma unroll
        for (int k4 = 0; k4 < BK; k4 += 4) {
            float4 a4[8];
#pragma unroll
            for (int i = 0; i < 8; i++)
                a4[i] = *reinterpret_cast<const float4*>(&As[st][ty * 8 + i][k4]);
#pragma unroll
            for (int kk = 0; kk < 4; kk++) {
                ull b2[TN / 2];
                {
                    float4 bv0 = *reinterpret_cast<const float4*>(&Bs[st][k4 + kk][tx * TN]);
                    b2[0] = pk2(bv0.x, bv0.y);
                    b2[1] = pk2(bv0.z, bv0.w);
                    if (TN == 8) {
                        float4 bv1 = *reinterpret_cast<const float4*>(&Bs[st][k4 + kk][tx * TN + 4]);
                        b2[2] = pk2(bv1.x, bv1.y);
                        b2[3] = pk2(bv1.z, bv1.w);
                    }
                }
#pragma unroll
                for (int i = 0; i < 8; i++) {
                    float av = (kk == 0) ? a4[i].x : (kk == 1) ? a4[i].y : (kk == 2) ? a4[i].z : a4[i].w;
                    ull a2 = splat2(av);
#pragma unroll
                    for (int j = 0; j < TN / 2; j++) fma2(acc[i][j], a2, b2[j]);
                }
            }
        }
        __syncthreads();
    }

    float accf[8][TN];
#pragma unroll
    for (int i = 0; i < 8; i++)
#pragma unroll
        for (int j = 0; j < TN / 2; j++) upk2(acc[i][j], accf[i][2 * j], accf[i][2 * j + 1]);

    if (s_out) {
#pragma unroll
        for (int i = 0; i < 8; i++) {
            float ps = 0.f, pt = 0.f;
#pragma unroll
            for (int j = 0; j < TN; j++) {
                int col = tx * TN + j;
                ps += accf[i][j] * sh_att[col];
                pt += accf[i][j] * sh_att[BN + col];
            }
            if (BN == 128) {
#pragma unroll
                for (int off = 4; off; off >>= 1) {
                    ps += __shfl_xor_sync(0xFFFFFFFFu, ps, off);
                    pt += __shfl_xor_sync(0xFFFFFFFFu, pt, off);
                }
                if ((tx & 7) == 0) {
                    int head = tx >> 3;
                    int r = blockRow + ty * 8 + i;
                    if (r < M) {
                        s_out[r * 2 + head] = ps;
                        t_out[r * 2 + head] = pt;
                    }
                }
            } else {
#pragma unroll
                for (int off = 8; off; off >>= 1) {
                    ps += __shfl_xor_sync(0xFFFFFFFFu, ps, off);
                    pt += __shfl_xor_sync(0xFFFFFFFFu, pt, off);
                }
                if (tx == 0) {
                    int r = blockRow + ty * 8 + i;
                    if (r < M) {
                        s_out[r] = ps;
                        t_out[r] = pt;
                    }
                }
            }
        }
    }

#pragma unroll
    for (int i = 0; i < 8; i++) {
        int r = blockRow + ty * 8 + i;
        if (r >= M) continue;
#pragma unroll
        for (int j4 = 0; j4 < TN / 4; j4++) {
            int col = tx * TN + j4 * 4;
            float4 v;
            v.x = accf[i][j4 * 4 + 0];
            v.y = accf[i][j4 * 4 + 1];
            v.z = accf[i][j4 * 4 + 2];
            v.w = accf[i][j4 * 4 + 3];
            if (bias) {
                v.x += bias[col + 0]; v.y += bias[col + 1];
                v.z += bias[col + 2]; v.w += bias[col + 3];
            }
            if (relu) {
                v.x = fmaxf(v.x, 0.f); v.y = fmaxf(v.y, 0.f);
                v.z = fmaxf(v.z, 0.f); v.w = fmaxf(v.w, 0.f);
            }
            if (C2) {
                float* dst = (col < 64) ? C : C2;
                *reinterpret_cast<float4*>(&dst[(size_t)r * 64 + (col & 63)]) = v;
            } else {
                *reinterpret_cast<float4*>(&C[(size_t)r * BN + col]) = v;
            }
        }
    }
}

// ---------------- GAT aggregation: one WARP per dst node ----------------
template <int H, bool RELU>
__global__ void __launch_bounds__(256) k_aggw(const float* __restrict__ hin,
                                              const float* __restrict__ s,
                                              const float* __restrict__ t,
                                              const int* __restrict__ rowptr,
                                              const int* __restrict__ col,
                                              const float* __restrict__ bias,
                                              float* __restrict__ out, int n) {
    constexpr int W = H * 64;
    constexpr int C = W / 32;
    int node = (blockIdx.x * 256 + threadIdx.x) >> 5;
    if (node >= n) return;
    int lane = threadIdx.x & 31;
    int start = rowptr[node];
    int deg = rowptr[node + 1] - start;

    float tn[H];
#pragma unroll
    for (int h = 0; h < H; h++) tn[h] = t[node * H + h];

    // pass 1: max
    float m[H];
#pragma unroll
    for (int h = 0; h < H; h++) m[h] = -1e30f;
    for (int k = lane; k < deg; k += 32) {
        int src = col[start + k];
#pragma unroll
        for (int h = 0; h < H; h++) {
            float e = s[src * H + h] + tn[h];
            e = e > 0.f ? e : NEG_SLOPE * e;
            m[h] = fmaxf(m[h], e);
        }
    }
#pragma unroll
    for (int h = 0; h < H; h++)
#pragma unroll
        for (int off = 16; off; off >>= 1)
            m[h] = fmaxf(m[h], __shfl_xor_sync(0xFFFFFFFFu, m[h], off));

    // pass 2: sum of exp
    float sm[H];
#pragma unroll
    for (int h = 0; h < H; h++) sm[h] = 0.f;
    for (int k = lane; k < deg; k += 32) {
        int src = col[start + k];
#pragma unroll
        for (int h = 0; h < H; h++) {
            float e = s[src * H + h] + tn[h];
            e = e > 0.f ? e : NEG_SLOPE * e;
            sm[h] += __expf(e - m[h]);
        }
    }
    float inv[H];
#pragma unroll
    for (int h = 0; h < H; h++) {
#pragma unroll
        for (int off = 16; off; off >>= 1)
            sm[h] += __shfl_xor_sync(0xFFFFFFFFu, sm[h], off);
        inv[h] = 1.f / (sm[h] + 1e-16f);
    }

    // pass 3: weighted gather, 32-edge chunks broadcast via shfl
    float acc[C];
#pragma unroll
    for (int c = 0; c < C; c++) acc[c] = 0.f;
    for (int base = 0; base < deg; base += 32) {
        int k = base + lane;
        int src = 0;
        float al0 = 0.f, al1 = 0.f;
        if (k < deg) {
            src = col[start + k];
            {
                float e = s[src * H + 0] + tn[0];
                e = e > 0.f ? e : NEG_SLOPE * e;
                al0 = __expf(e - m[0]) * inv[0];
            }
            if (H == 2) {
                float e = s[src * H + 1] + tn[1];
                e = e > 0.f ? e : NEG_SLOPE * e;
                al1 = __expf(e - m[1]) * inv[1];
            }
        }
        int nk = min(32, deg - base);
        for (int e2 = 0; e2 < nk; e2++) {
            int sb = __shfl_sync(0xFFFFFFFFu, src, e2);
            float a0 = __shfl_sync(0xFFFFFFFFu, al0, e2);
            float a1 = (H == 2) ? __shfl_sync(0xFFFFFFFFu, al1, e2) : a0;
            const float* hp = hin + (size_t)sb * W;
#pragma unroll
            for (int c = 0; c < C; c++) {
                float a = (H == 2) ? ((c < 2) ? a0 : a1) : a0;
                acc[c] = fmaf(a, hp[lane + 32 * c], acc[c]);
            }
        }
    }

#pragma unroll
    for (int c = 0; c < C; c++) {
        float v = acc[c] + bias[lane + 32 * c];
        if (RELU) v = fmaxf(v, 0.f);
        out[(size_t)node * W + lane + 32 * c] = v;
    }
}

// ---------------- host launch ----------------
extern "C" void kernel_launch(void* const* d_in, const int* in_sizes, int n_in,
                              void* d_out, int out_size) {
    const float* x     = (const float*)d_in[0];
    const int*   ei    = (const int*)d_in[1];
    const float* W0    = (const float*)d_in[2];
    const float* as0   = (const float*)d_in[3];
    const float* ad0   = (const float*)d_in[4];
    const float* b0    = (const float*)d_in[5];
    const float* W1    = (const float*)d_in[6];
    const float* as1   = (const float*)d_in[7];
    const float* ad1   = (const float*)d_in[8];
    const float* b1    = (const float*)d_in[9];
    const float* W2    = (const float*)d_in[10];
    const float* as2   = (const float*)d_in[11];
    const float* ad2   = (const float*)d_in[12];
    const float* b2    = (const float*)d_in[13];
    const float* Wv    = (const float*)d_in[14];
    const float* bv    = (const float*)d_in[15];
    const float* Wt    = (const float*)d_in[16];
    const float* bt    = (const float*)d_in[17];

    int N = in_sizes[0] / 512;
    int E = in_sizes[1] / 2;

    float* out = (float*)d_out;
    float* h_out = out;
    float* vis = out + (size_t)N * 64;
    float* txt = out + (size_t)N * 64 * 2;

    float *h0, *h1, *sA, *tA, *Wcat, *bcat;
    int *deg, *rowptr, *cursor, *colA, *bsum, *bexc;
    cudaGetSymbolAddress((void**)&h0, g_h0);
    cudaGetSymbolAddress((void**)&h1, g_h1);
    cudaGetSymbolAddress((void**)&sA, g_s);
    cudaGetSymbolAddress((void**)&tA, g_t);
    cudaGetSymbolAddress((void**)&deg, g_deg);
    cudaGetSymbolAddress((void**)&rowptr, g_rowptr);
    cudaGetSymbolAddress((void**)&cursor, g_cursor);
    cudaGetSymbolAddress((void**)&colA, g_col);
    cudaGetSymbolAddress((void**)&bsum, g_bsum);
    cudaGetSymbolAddress((void**)&bexc, g_bexc);
    cudaGetSymbolAddress((void**)&Wcat, g_Wcat);
    cudaGetSymbolAddress((void**)&bcat, g_bcat);

    int nb = (N + 255) / 256;    // 196
    int gblk = (N + 127) / 128;  // 391
    int wgrid = (N * 32 + 255) / 256;  // warp-per-node grids

    // launches 0-2: CSR front half
    k_init_deg<<<nb, 256>>>(deg, N);
    k_hist<<<(E + 255) / 256, 256>>>(ei, E, deg);
    k_blocksums<<<nb, 256>>>(deg, bsum, N);
    // launch 3: layer-0 GEMM (ncu capture slot)
    k_gemm<128><<<gblk, 256>>>(x, W0, h0, nullptr, N, 512, nullptr, 0, as0, ad0, sA, tA);
    // CSR back half
    k_scan_top<<<1, 256>>>(bsum, bexc, nb);
    k_scan_apply<<<nb, 256>>>(deg, bexc, rowptr, cursor, colA, N);
    k_scatter<<<(E + 255) / 256, 256>>>(ei, E, cursor, colA);

    // ---- layer 0 aggregation ----
    k_aggw<2, true><<<wgrid, 256>>>(h0, sA, tA, rowptr, colA, b0, h1, N);

    // ---- layer 1 ----
    k_gemm<128><<<gblk, 256>>>(h1, W1, h0, nullptr, N, 128, nullptr, 0, as1, ad1, sA, tA);
    k_aggw<2, true><<<wgrid, 256>>>(h0, sA, tA, rowptr, colA, b1, h1, N);

    // ---- layer 2 (heads=1, no relu) ----
    k_gemm<64><<<gblk, 256>>>(h1, W2, h0, nullptr, N, 128, nullptr, 0, as2, ad2, sA, tA);
    k_aggw<1, false><<<wgrid, 256>>>(h0, sA, tA, rowptr, colA, b2, h_out, N);

    // ---- MLP heads: one combined GEMM with split store ----
    k_prep<<<(64 * 128 + 255) / 256, 256>>>(Wv, bv, Wt, bt, Wcat, bcat);
    k_gemm<128><<<gblk, 256>>>(h_out, Wcat, vis, txt, N, 64, bcat, 1,
                               nullptr, nullptr, nullptr, nullptr);
}

// round 6
// speedup vs baseline: 2.1209x; 1.0775x over previous
#include <cuda_runtime.h>
#include <cstdint>

#define NNODES 50000
#define NEDGES 800000
#define TOTEDGES (NEDGES + NNODES)
#define NEG_SLOPE 0.2f

// ---------------- scratch (allocation-free: device globals) ----------------
__device__ float g_h0[(size_t)NNODES * 128];
__device__ float g_h1[(size_t)NNODES * 128];
__device__ float g_s[NNODES * 2];
__device__ float g_t[NNODES * 2];
__device__ int   g_deg[NNODES];
__device__ int   g_rowptr[NNODES + 1];
__device__ int   g_cursor[NNODES];
__device__ int   g_col[TOTEDGES];
__device__ int   g_bsum[256];
__device__ int   g_bexc[256];
__device__ float g_Wcat[64 * 128];
__device__ float g_bcat[128];

// ---------------- helpers ----------------
__device__ __forceinline__ uint32_t smem_u32(const void* p) {
    return (uint32_t)__cvta_generic_to_shared(p);
}
typedef unsigned long long ull;
__device__ __forceinline__ ull pk2(float x, float y) {
    ull r;
    asm("mov.b64 %0, {%1, %2};" : "=l"(r) : "f"(x), "f"(y));
    return r;
}
__device__ __forceinline__ ull splat2(float x) {
    ull r;
    asm("mov.b64 %0, {%1, %1};" : "=l"(r) : "f"(x));
    return r;
}
__device__ __forceinline__ void fma2(ull& d, ull a, ull b) {
    asm("fma.rn.f32x2 %0, %1, %2, %3;" : "=l"(d) : "l"(a), "l"(b), "l"(d));
}
__device__ __forceinline__ void upk2(ull v, float& lo, float& hi) {
    asm("mov.b64 {%0, %1}, %2;" : "=f"(lo), "=f"(hi) : "l"(v));
}
__device__ __forceinline__ void cpa16(uint32_t dst, const void* src) {
    asm volatile("cp.async.cg.shared.global [%0], [%1], 16;" :: "r"(dst), "l"(src));
}

// ---------------- CSR build ----------------
__global__ void k_init_deg(int* __restrict__ deg, int n) {
    int i = blockIdx.x * blockDim.x + threadIdx.x;
    if (i < n) deg[i] = 1;
}
__global__ void k_hist(const int* __restrict__ ei, int e, int* __restrict__ deg) {
    int i = blockIdx.x * blockDim.x + threadIdx.x;
    if (i < e) atomicAdd(&deg[ei[e + i]], 1);
}
__global__ void k_blocksums(const int* __restrict__ deg, int* __restrict__ bsum, int n) {
    __shared__ int wred[8];
    int i = blockIdx.x * 256 + threadIdx.x;
    int v = (i < n) ? deg[i] : 0;
    int lane = threadIdx.x & 31, w = threadIdx.x >> 5;
#pragma unroll
    for (int off = 16; off; off >>= 1) v += __shfl_xor_sync(0xFFFFFFFFu, v, off);
    if (lane == 0) wred[w] = v;
    __syncthreads();
    if (threadIdx.x == 0) {
        int s = 0;
#pragma unroll
        for (int k = 0; k < 8; k++) s += wred[k];
        bsum[blockIdx.x] = s;
    }
}
__global__ void k_scan_top(const int* __restrict__ bsum, int* __restrict__ bexc, int nb) {
    __shared__ int wred[8];
    int tid = threadIdx.x, lane = tid & 31, w = tid >> 5;
    int v = (tid < nb) ? bsum[tid] : 0;
    int x = v;
#pragma unroll
    for (int off = 1; off < 32; off <<= 1) {
        int y = __shfl_up_sync(0xFFFFFFFFu, x, off);
        if (lane >= off) x += y;
    }
    if (lane == 31) wred[w] = x;
    __syncthreads();
    if (w == 0) {
        int sv = (lane < 8) ? wred[lane] : 0;
#pragma unroll
        for (int off = 1; off < 8; off <<= 1) {
            int y = __shfl_up_sync(0xFFFFFFFFu, sv, off);
            if (lane >= off) sv += y;
        }
        if (lane < 8) wred[lane] = sv;
    }
    __syncthreads();
    int woff = (w > 0) ? wred[w - 1] : 0;
    if (tid < nb) bexc[tid] = x + woff - v;
}
__global__ void k_scan_apply(const int* __restrict__ deg, const int* __restrict__ bexc,
                             int* __restrict__ rowptr, int* __restrict__ cursor,
                             int* __restrict__ col, int n) {
    __shared__ int wred[8];
    int i = blockIdx.x * 256 + threadIdx.x;
    int tid = threadIdx.x, lane = tid & 31, w = tid >> 5;
    int v = (i < n) ? deg[i] : 0;
    int x = v;
#pragma unroll
    for (int off = 1; off < 32; off <<= 1) {
        int y = __shfl_up_sync(0xFFFFFFFFu, x, off);
        if (lane >= off) x += y;
    }
    if (lane == 31) wred[w] = x;
    __syncthreads();
    if (w == 0) {
        int sv = (lane < 8) ? wred[lane] : 0;
#pragma unroll
        for (int off = 1; off < 8; off <<= 1) {
            int y = __shfl_up_sync(0xFFFFFFFFu, sv, off);
            if (lane >= off) sv += y;
        }
        if (lane < 8) wred[lane] = sv;
    }
    __syncthreads();
    int woff = (w > 0) ? wred[w - 1] : 0;
    if (i < n) {
        int incl = x + woff + bexc[blockIdx.x];
        rowptr[i + 1] = incl;
        int p = incl - v;
        col[p] = i;
        cursor[i] = p + 1;
        if (i == 0) rowptr[0] = 0;
    }
}
__global__ void k_scatter(const int* __restrict__ ei, int e, int* __restrict__ cursor,
                          int* __restrict__ col) {
    int i = blockIdx.x * blockDim.x + threadIdx.x;
    if (i < e) {
        int s = ei[i];
        int d = ei[e + i];
        int p = atomicAdd(&cursor[d], 1);
        col[p] = s;
    }
}

// ---------------- Wcat prep ----------------
__global__ void k_prep(const float* __restrict__ Wv, const float* __restrict__ bv,
                       const float* __restrict__ Wt, const float* __restrict__ bt,
                       float* __restrict__ Wcat, float* __restrict__ bcat) {
    int i = blockIdx.x * blockDim.x + threadIdx.x;
    if (i < 64 * 128) {
        int k = i >> 7, n = i & 127;
        Wcat[i] = (n < 64) ? Wv[k * 64 + n] : Wt[k * 64 + (n - 64)];
    }
    if (i < 128) bcat[i] = (i < 64) ? bv[i] : bt[i - 64];
}

// ---------------- f32x2 GEMM: C[M,BN] = A[M,K] @ B[K,BN] ----------------
// 2 CTAs/SM (regs capped at 128): per-row epilogue to keep pressure low.
template <int BN>
__global__ void __launch_bounds__(256, 2) k_gemm(
    const float* __restrict__ A, const float* __restrict__ B,
    float* __restrict__ C, float* __restrict__ C2, int M, int K,
    const float* __restrict__ bias, int relu,
    const float* __restrict__ a_src, const float* __restrict__ a_dst,
    float* __restrict__ s_out, float* __restrict__ t_out)
{
    constexpr int BM = 128, BK = 16, TN = BN / 16;
    __shared__ float As[2][BM][BK];
    __shared__ float Bs[2][BK][BN];
    __shared__ float sh_att[2 * BN];

    int tid = threadIdx.x;
    int tx = tid & 15, ty = tid >> 4;
    int blockRow = blockIdx.x * BM;

    if (a_src) {
        if (tid < BN) sh_att[tid] = a_src[tid];
        else if (tid < 2 * BN) sh_att[tid] = a_dst[tid - BN];
    }

    ull acc[8][TN / 2];
#pragma unroll
    for (int i = 0; i < 8; i++)
#pragma unroll
        for (int j = 0; j < TN / 2; j++) acc[i][j] = 0ull;

    int nch = K / BK;

    auto loadA = [&](int c, int st) {
        int k0 = c * BK;
#pragma unroll
        for (int l = 0; l < 2; l++) {
            int f = tid + l * 256;
            int row = f >> 2, q = f & 3;
            int gr = blockRow + row;
            if (gr >= M) gr = M - 1;
            cpa16(smem_u32(&As[st][row][q * 4]), &A[(size_t)gr * K + k0 + q * 4]);
        }
    };
    auto loadB = [&](int c, int st) {
        int k0 = c * BK;
        constexpr int CH = BK * BN / 4;
#pragma unroll
        for (int l = 0; l < CH / 256; l++) {
            int f = tid + l * 256;
            int kr = f / (BN / 4), q = f % (BN / 4);
            cpa16(smem_u32(&Bs[st][kr][q * 4]), &B[(size_t)(k0 + kr) * BN + q * 4]);
        }
    };

    loadA(0, 0);
    loadB(0, 0);
    asm volatile("cp.async.commit_group;");

    for (int c = 0; c < nch; c++) {
        int st = c & 1;
        if (c + 1 < nch) {
            loadA(c + 1, (c + 1) & 1);
            loadB(c + 1, (c + 1) & 1);
            asm volatile("cp.async.commit_group;");
            asm volatile("cp.async.wait_group 1;");
        } else {
            asm volatile("cp.async.wait_group 0;");
        }
        __syncthreads();

#pragma unroll
        for (int k4 = 0; k4 < BK; k4 += 4) {
            float4 a4[8];
#pragma unroll
            for (int i = 0; i < 8; i++)
                a4[i] = *reinterpret_cast<const float4*>(&As[st][ty * 8 + i][k4]);
#pragma unroll
            for (int kk = 0; kk < 4; kk++) {
                ull b2[TN / 2];
                {
                    float4 bv0 = *reinterpret_cast<const float4*>(&Bs[st][k4 + kk][tx * TN]);
                    b2[0] = pk2(bv0.x, bv0.y);
                    b2[1] = pk2(bv0.z, bv0.w);
                    if (TN == 8) {
                        float4 bv1 = *reinterpret_cast<const float4*>(&Bs[st][k4 + kk][tx * TN + 4]);
                        b2[2] = pk2(bv1.x, bv1.y);
                        b2[3] = pk2(bv1.z, bv1.w);
                    }
                }
#pragma unroll
                for (int i = 0; i < 8; i++) {
                    float av = (kk == 0) ? a4[i].x : (kk == 1) ? a4[i].y : (kk == 2) ? a4[i].z : a4[i].w;
                    ull a2 = splat2(av);
#pragma unroll
                    for (int j = 0; j < TN / 2; j++) fma2(acc[i][j], a2, b2[j]);
                }
            }
        }
        __syncthreads();
    }

    // ---- per-row epilogue (keeps register pressure low) ----
#pragma unroll
    for (int i = 0; i < 8; i++) {
        int r = blockRow + ty * 8 + i;
        float af[TN];
#pragma unroll
        for (int j = 0; j < TN / 2; j++) upk2(acc[i][j], af[2 * j], af[2 * j + 1]);

        if (s_out) {
            float ps = 0.f, pt = 0.f;
#pragma unroll
            for (int j = 0; j < TN; j++) {
                int col = tx * TN + j;
                ps += af[j] * sh_att[col];
                pt += af[j] * sh_att[BN + col];
            }
            if (BN == 128) {
#pragma unroll
                for (int off = 4; off; off >>= 1) {
                    ps += __shfl_xor_sync(0xFFFFFFFFu, ps, off);
                    pt += __shfl_xor_sync(0xFFFFFFFFu, pt, off);
                }
                if ((tx & 7) == 0 && r < M) {
                    int head = tx >> 3;
                    s_out[r * 2 + head] = ps;
                    t_out[r * 2 + head] = pt;
                }
            } else {
#pragma unroll
                for (int off = 8; off; off >>= 1) {
                    ps += __shfl_xor_sync(0xFFFFFFFFu, ps, off);
                    pt += __shfl_xor_sync(0xFFFFFFFFu, pt, off);
                }
                if (tx == 0 && r < M) {
                    s_out[r] = ps;
                    t_out[r] = pt;
                }
            }
        }

        if (r < M) {
#pragma unroll
            for (int j4 = 0; j4 < TN / 4; j4++) {
                int col = tx * TN + j4 * 4;
                float4 v;
                v.x = af[j4 * 4 + 0];
                v.y = af[j4 * 4 + 1];
                v.z = af[j4 * 4 + 2];
                v.w = af[j4 * 4 + 3];
                if (bias) {
                    v.x += bias[col + 0]; v.y += bias[col + 1];
                    v.z += bias[col + 2]; v.w += bias[col + 3];
                }
                if (relu) {
                    v.x = fmaxf(v.x, 0.f); v.y = fmaxf(v.y, 0.f);
                    v.z = fmaxf(v.z, 0.f); v.w = fmaxf(v.w, 0.f);
                }
                if (C2) {
                    float* dst = (col < 64) ? C : C2;
                    *reinterpret_cast<float4*>(&dst[(size_t)r * 64 + (col & 63)]) = v;
                } else {
                    *reinterpret_cast<float4*>(&C[(size_t)r * BN + col]) = v;
                }
            }
        }
    }
}

// ---------------- GAT aggregation: one WARP per dst node ----------------
template <int H, bool RELU>
__global__ void __launch_bounds__(256) k_aggw(const float* __restrict__ hin,
                                              const float* __restrict__ s,
                                              const float* __restrict__ t,
                                              const int* __restrict__ rowptr,
                                              const int* __restrict__ col,
                                              const float* __restrict__ bias,
                                              float* __restrict__ out, int n) {
    constexpr int W = H * 64;
    constexpr int C = W / 32;
    int node = (blockIdx.x * 256 + threadIdx.x) >> 5;
    if (node >= n) return;
    int lane = threadIdx.x & 31;
    int start = rowptr[node];
    int deg = rowptr[node + 1] - start;

    float tn[H];
#pragma unroll
    for (int h = 0; h < H; h++) tn[h] = t[node * H + h];

    float m[H];
#pragma unroll
    for (int h = 0; h < H; h++) m[h] = -1e30f;
    for (int k = lane; k < deg; k += 32) {
        int src = col[start + k];
#pragma unroll
        for (int h = 0; h < H; h++) {
            float e = s[src * H + h] + tn[h];
            e = e > 0.f ? e : NEG_SLOPE * e;
            m[h] = fmaxf(m[h], e);
        }
    }
#pragma unroll
    for (int h = 0; h < H; h++)
#pragma unroll
        for (int off = 16; off; off >>= 1)
            m[h] = fmaxf(m[h], __shfl_xor_sync(0xFFFFFFFFu, m[h], off));

    float sm[H];
#pragma unroll
    for (int h = 0; h < H; h++) sm[h] = 0.f;
    for (int k = lane; k < deg; k += 32) {
        int src = col[start + k];
#pragma unroll
        for (int h = 0; h < H; h++) {
            float e = s[src * H + h] + tn[h];
            e = e > 0.f ? e : NEG_SLOPE * e;
            sm[h] += __expf(e - m[h]);
        }
    }
    float inv[H];
#pragma unroll
    for (int h = 0; h < H; h++) {
#pragma unroll
        for (int off = 16; off; off >>= 1)
            sm[h] += __shfl_xor_sync(0xFFFFFFFFu, sm[h], off);
        inv[h] = 1.f / (sm[h] + 1e-16f);
    }

    float acc[C];
#pragma unroll
    for (int c = 0; c < C; c++) acc[c] = 0.f;
    for (int base = 0; base < deg; base += 32) {
        int k = base + lane;
        int src = 0;
        float al0 = 0.f, al1 = 0.f;
        if (k < deg) {
            src = col[start + k];
            {
                float e = s[src * H + 0] + tn[0];
                e = e > 0.f ? e : NEG_SLOPE * e;
                al0 = __expf(e - m[0]) * inv[0];
            }
            if (H == 2) {
                float e = s[src * H + 1] + tn[1];
                e = e > 0.f ? e : NEG_SLOPE * e;
                al1 = __expf(e - m[1]) * inv[1];
            }
        }
        int nk = min(32, deg - base);
        for (int e2 = 0; e2 < nk; e2++) {
            int sb = __shfl_sync(0xFFFFFFFFu, src, e2);
            float a0 = __shfl_sync(0xFFFFFFFFu, al0, e2);
            float a1 = (H == 2) ? __shfl_sync(0xFFFFFFFFu, al1, e2) : a0;
            const float* hp = hin + (size_t)sb * W;
#pragma unroll
            for (int c = 0; c < C; c++) {
                float a = (H == 2) ? ((c < 2) ? a0 : a1) : a0;
                acc[c] = fmaf(a, hp[lane + 32 * c], acc[c]);
            }
        }
    }

#pragma unroll
    for (int c = 0; c < C; c++) {
        float v = acc[c] + bias[lane + 32 * c];
        if (RELU) v = fmaxf(v, 0.f);
        out[(size_t)node * W + lane + 32 * c] = v;
    }
}

// ---------------- host launch ----------------
extern "C" void kernel_launch(void* const* d_in, const int* in_sizes, int n_in,
                              void* d_out, int out_size) {
    const float* x     = (const float*)d_in[0];
    const int*   ei    = (const int*)d_in[1];
    const float* W0    = (const float*)d_in[2];
    const float* as0   = (const float*)d_in[3];
    const float* ad0   = (const float*)d_in[4];
    const float* b0    = (const float*)d_in[5];
    const float* W1    = (const float*)d_in[6];
    const float* as1   = (const float*)d_in[7];
    const float* ad1   = (const float*)d_in[8];
    const float* b1    = (const float*)d_in[9];
    const float* W2    = (const float*)d_in[10];
    const float* as2   = (const float*)d_in[11];
    const float* ad2   = (const float*)d_in[12];
    const float* b2    = (const float*)d_in[13];
    const float* Wv    = (const float*)d_in[14];
    const float* bv    = (const float*)d_in[15];
    const float* Wt    = (const float*)d_in[16];
    const float* bt    = (const float*)d_in[17];

    int N = in_sizes[0] / 512;
    int E = in_sizes[1] / 2;

    float* out = (float*)d_out;
    float* h_out = out;
    float* vis = out + (size_t)N * 64;
    float* txt = out + (size_t)N * 64 * 2;

    float *h0, *h1, *sA, *tA, *Wcat, *bcat;
    int *deg, *rowptr, *cursor, *colA, *bsum, *bexc;
    cudaGetSymbolAddress((void**)&h0, g_h0);
    cudaGetSymbolAddress((void**)&h1, g_h1);
    cudaGetSymbolAddress((void**)&sA, g_s);
    cudaGetSymbolAddress((void**)&tA, g_t);
    cudaGetSymbolAddress((void**)&deg, g_deg);
    cudaGetSymbolAddress((void**)&rowptr, g_rowptr);
    cudaGetSymbolAddress((void**)&cursor, g_cursor);
    cudaGetSymbolAddress((void**)&colA, g_col);
    cudaGetSymbolAddress((void**)&bsum, g_bsum);
    cudaGetSymbolAddress((void**)&bexc, g_bexc);
    cudaGetSymbolAddress((void**)&Wcat, g_Wcat);
    cudaGetSymbolAddress((void**)&bcat, g_bcat);

    int nb = (N + 255) / 256;
    int gblk = (N + 127) / 128;
    int wgrid = (N * 32 + 255) / 256;

    // launches 0-2: CSR front half
    k_init_deg<<<nb, 256>>>(deg, N);
    k_hist<<<(E + 255) / 256, 256>>>(ei, E, deg);
    k_blocksums<<<nb, 256>>>(deg, bsum, N);
    // launch 3: layer-0 GEMM (ncu capture slot)
    k_gemm<128><<<gblk, 256>>>(x, W0, h0, nullptr, N, 512, nullptr, 0, as0, ad0, sA, tA);
    // CSR back half
    k_scan_top<<<1, 256>>>(bsum, bexc, nb);
    k_scan_apply<<<nb, 256>>>(deg, bexc, rowptr, cursor, colA, N);
    k_scatter<<<(E + 255) / 256, 256>>>(ei, E, cursor, colA);

    // ---- layer 0 aggregation ----
    k_aggw<2, true><<<wgrid, 256>>>(h0, sA, tA, rowptr, colA, b0, h1, N);

    // ---- layer 1 ----
    k_gemm<128><<<gblk, 256>>>(h1, W1, h0, nullptr, N, 128, nullptr, 0, as1, ad1, sA, tA);
    k_aggw<2, true><<<wgrid, 256>>>(h0, sA, tA, rowptr, colA, b1, h1, N);

    // ---- layer 2 (heads=1, no relu) ----
    k_gemm<64><<<gblk, 256>>>(h1, W2, h0, nullptr, N, 128, nullptr, 0, as2, ad2, sA, tA);
    k_aggw<1, false><<<wgrid, 256>>>(h0, sA, tA, rowptr, colA, b2, h_out, N);

    // ---- MLP heads: one combined GEMM with split store ----
    k_prep<<<(64 * 128 + 255) / 256, 256>>>(Wv, bv, Wt, bt, Wcat, bcat);
    k_gemm<128><<<gblk, 256>>>(h_out, Wcat, vis, txt, N, 64, bcat, 1,
                               nullptr, nullptr, nullptr, nullptr);
}

// round 7
// speedup vs baseline: 2.2195x; 1.0465x over previous
#include <cuda_runtime.h>
#include <cstdint>

#define NNODES 50000
#define NEDGES 800000
#define TOTEDGES (NEDGES + NNODES)
#define NEG_SLOPE 0.2f

// ---------------- scratch (allocation-free: device globals) ----------------
__device__ float g_h0[(size_t)NNODES * 128];
__device__ float g_h1[(size_t)NNODES * 128];
__device__ float g_s[NNODES * 2];
__device__ float g_t[NNODES * 2];
__device__ int   g_deg[NNODES];
__device__ int   g_rowptr[NNODES + 1];
__device__ int   g_cursor[NNODES];
__device__ int   g_col[TOTEDGES];
__device__ int   g_bsum[256];
__device__ int   g_bexc[256];
__device__ float g_Wcat[64 * 128];
__device__ float g_bcat[128];

// ---------------- helpers ----------------
__device__ __forceinline__ uint32_t smem_u32(const void* p) {
    return (uint32_t)__cvta_generic_to_shared(p);
}
typedef unsigned long long ull;
union F4U { float4 f; ull u[2]; };
__device__ __forceinline__ ull splat2(float x) {
    ull r;
    asm("mov.b64 %0, {%1, %1};" : "=l"(r) : "f"(x));
    return r;
}
__device__ __forceinline__ void fma2(ull& d, ull a, ull b) {
    asm("fma.rn.f32x2 %0, %1, %2, %3;" : "=l"(d) : "l"(a), "l"(b), "l"(d));
}
__device__ __forceinline__ void upk2(ull v, float& lo, float& hi) {
    asm("mov.b64 {%0, %1}, %2;" : "=f"(lo), "=f"(hi) : "l"(v));
}
__device__ __forceinline__ void cpa16(uint32_t dst, const void* src) {
    asm volatile("cp.async.cg.shared.global [%0], [%1], 16;" :: "r"(dst), "l"(src));
}

// ---------------- CSR build ----------------
__global__ void k_init_deg(int* __restrict__ deg, int n) {
    int i = blockIdx.x * blockDim.x + threadIdx.x;
    if (i < n) deg[i] = 1;
}
__global__ void k_hist(const int* __restrict__ ei, int e, int* __restrict__ deg) {
    int i = blockIdx.x * blockDim.x + threadIdx.x;
    if (i < e) atomicAdd(&deg[ei[e + i]], 1);
}
__global__ void k_blocksums(const int* __restrict__ deg, int* __restrict__ bsum, int n) {
    __shared__ int wred[8];
    int i = blockIdx.x * 256 + threadIdx.x;
    int v = (i < n) ? deg[i] : 0;
    int lane = threadIdx.x & 31, w = threadIdx.x >> 5;
#pragma unroll
    for (int off = 16; off; off >>= 1) v += __shfl_xor_sync(0xFFFFFFFFu, v, off);
    if (lane == 0) wred[w] = v;
    __syncthreads();
    if (threadIdx.x == 0) {
        int s = 0;
#pragma unroll
        for (int k = 0; k < 8; k++) s += wred[k];
        bsum[blockIdx.x] = s;
    }
}
__global__ void k_scan_top(const int* __restrict__ bsum, int* __restrict__ bexc, int nb) {
    __shared__ int wred[8];
    int tid = threadIdx.x, lane = tid & 31, w = tid >> 5;
    int v = (tid < nb) ? bsum[tid] : 0;
    int x = v;
#pragma unroll
    for (int off = 1; off < 32; off <<= 1) {
        int y = __shfl_up_sync(0xFFFFFFFFu, x, off);
        if (lane >= off) x += y;
    }
    if (lane == 31) wred[w] = x;
    __syncthreads();
    if (w == 0) {
        int sv = (lane < 8) ? wred[lane] : 0;
#pragma unroll
        for (int off = 1; off < 8; off <<= 1) {
            int y = __shfl_up_sync(0xFFFFFFFFu, sv, off);
            if (lane >= off) sv += y;
        }
        if (lane < 8) wred[lane] = sv;
    }
    __syncthreads();
    int woff = (w > 0) ? wred[w - 1] : 0;
    if (tid < nb) bexc[tid] = x + woff - v;
}
__global__ void k_scan_apply(const int* __restrict__ deg, const int* __restrict__ bexc,
                             int* __restrict__ rowptr, int* __restrict__ cursor,
                             int* __restrict__ col, int n) {
    __shared__ int wred[8];
    int i = blockIdx.x * 256 + threadIdx.x;
    int tid = threadIdx.x, lane = tid & 31, w = tid >> 5;
    int v = (i < n) ? deg[i] : 0;
    int x = v;
#pragma unroll
    for (int off = 1; off < 32; off <<= 1) {
        int y = __shfl_up_sync(0xFFFFFFFFu, x, off);
        if (lane >= off) x += y;
    }
    if (lane == 31) wred[w] = x;
    __syncthreads();
    if (w == 0) {
        int sv = (lane < 8) ? wred[lane] : 0;
#pragma unroll
        for (int off = 1; off < 8; off <<= 1) {
            int y = __shfl_up_sync(0xFFFFFFFFu, sv, off);
            if (lane >= off) sv += y;
        }
        if (lane < 8) wred[lane] = sv;
    }
    __syncthreads();
    int woff = (w > 0) ? wred[w - 1] : 0;
    if (i < n) {
        int incl = x + woff + bexc[blockIdx.x];
        rowptr[i + 1] = incl;
        int p = incl - v;
        col[p] = i;
        cursor[i] = p + 1;
        if (i == 0) rowptr[0] = 0;
    }
}
__global__ void k_scatter(const int* __restrict__ ei, int e, int* __restrict__ cursor,
                          int* __restrict__ col) {
    int i = blockIdx.x * blockDim.x + threadIdx.x;
    if (i < e) {
        int s = ei[i];
        int d = ei[e + i];
        int p = atomicAdd(&cursor[d], 1);
        col[p] = s;
    }
}

// ---------------- Wcat prep ----------------
__global__ void k_prep(const float* __restrict__ Wv, const float* __restrict__ bv,
                       const float* __restrict__ Wt, const float* __restrict__ bt,
                       float* __restrict__ Wcat, float* __restrict__ bcat) {
    int i = blockIdx.x * blockDim.x + threadIdx.x;
    if (i < 64 * 128) {
        int k = i >> 7, n = i & 127;
        Wcat[i] = (n < 64) ? Wv[k * 64 + n] : Wt[k * 64 + (n - 64)];
    }
    if (i < 128) bcat[i] = (i < 64) ? bv[i] : bt[i - 64];
}

// ---------------- f32x2 GEMM: C[M,BN] = A[M,K] @ B[K,BN] ----------------
template <int BN>
__global__ void __launch_bounds__(256, 2) k_gemm(
    const float* __restrict__ A, const float* __restrict__ B,
    float* __restrict__ C, float* __restrict__ C2, int M, int K,
    const float* __restrict__ bias, int relu,
    const float* __restrict__ a_src, const float* __restrict__ a_dst,
    float* __restrict__ s_out, float* __restrict__ t_out)
{
    constexpr int BM = 128, BK = 16, TN = BN / 16;
    __shared__ float As[2][BM][BK];
    __shared__ float Bs[2][BK][BN];
    __shared__ float sh_att[2 * BN];

    int tid = threadIdx.x;
    int tx = tid & 15, ty = tid >> 4;
    int blockRow = blockIdx.x * BM;

    if (a_src) {
        if (tid < BN) sh_att[tid] = a_src[tid];
        else if (tid < 2 * BN) sh_att[tid] = a_dst[tid - BN];
    }

    ull acc[8][TN / 2];
#pragma unroll
    for (int i = 0; i < 8; i++)
#pragma unroll
        for (int j = 0; j < TN / 2; j++) acc[i][j] = 0ull;

    int nch = K / BK;

    auto loadA = [&](int c, int st) {
        int k0 = c * BK;
#pragma unroll
        for (int l = 0; l < 2; l++) {
            int f = tid + l * 256;
            int row = f >> 2, q = f & 3;
            int gr = blockRow + row;
            if (gr >= M) gr = M - 1;
            cpa16(smem_u32(&As[st][row][q * 4]), &A[(size_t)gr * K + k0 + q * 4]);
        }
    };
    auto loadB = [&](int c, int st) {
        int k0 = c * BK;
        constexpr int CH = BK * BN / 4;
#pragma unroll
        for (int l = 0; l < CH / 256; l++) {
            int f = tid + l * 256;
            int kr = f / (BN / 4), q = f % (BN / 4);
            cpa16(smem_u32(&Bs[st][kr][q * 4]), &B[(size_t)(k0 + kr) * BN + q * 4]);
        }
    };

    loadA(0, 0);
    loadB(0, 0);
    asm volatile("cp.async.commit_group;");

    for (int c = 0; c < nch; c++) {
        int st = c & 1;
        if (c + 1 < nch) {
            loadA(c + 1, (c + 1) & 1);
            loadB(c + 1, (c + 1) & 1);
            asm volatile("cp.async.commit_group;");
            asm volatile("cp.async.wait_group 1;");
        } else {
            asm volatile("cp.async.wait_group 0;");
        }
        __syncthreads();

#pragma unroll
        for (int k4 = 0; k4 < BK; k4 += 4) {
            float4 a4[8];
#pragma unroll
            for (int i = 0; i < 8; i++)
                a4[i] = *reinterpret_cast<const float4*>(&As[st][ty * 8 + i][k4]);
#pragma unroll
            for (int kk = 0; kk < 4; kk++) {
                // B pairs loaded directly as 64-bit register pairs (no pack movs)
                ull b2[TN / 2];
                {
                    F4U bu0;
                    bu0.f = *reinterpret_cast<const float4*>(&Bs[st][k4 + kk][tx * TN]);
                    b2[0] = bu0.u[0];
                    b2[1] = bu0.u[1];
                    if (TN == 8) {
                        F4U bu1;
                        bu1.f = *reinterpret_cast<const float4*>(&Bs[st][k4 + kk][tx * TN + 4]);
                        b2[2] = bu1.u[0];
                        b2[3] = bu1.u[1];
                    }
                }
#pragma unroll
                for (int i = 0; i < 8; i++) {
                    float av = (kk == 0) ? a4[i].x : (kk == 1) ? a4[i].y : (kk == 2) ? a4[i].z : a4[i].w;
                    ull a2 = splat2(av);
#pragma unroll
                    for (int j = 0; j < TN / 2; j++) fma2(acc[i][j], a2, b2[j]);
                }
            }
        }
        __syncthreads();
    }

    // ---- per-row epilogue ----
#pragma unroll
    for (int i = 0; i < 8; i++) {
        int r = blockRow + ty * 8 + i;
        float af[TN];
#pragma unroll
        for (int j = 0; j < TN / 2; j++) upk2(acc[i][j], af[2 * j], af[2 * j + 1]);

        if (s_out) {
            float ps = 0.f, pt = 0.f;
#pragma unroll
            for (int j = 0; j < TN; j++) {
                int col = tx * TN + j;
                ps += af[j] * sh_att[col];
                pt += af[j] * sh_att[BN + col];
            }
            if (BN == 128) {
#pragma unroll
                for (int off = 4; off; off >>= 1) {
                    ps += __shfl_xor_sync(0xFFFFFFFFu, ps, off);
                    pt += __shfl_xor_sync(0xFFFFFFFFu, pt, off);
                }
                if ((tx & 7) == 0 && r < M) {
                    int head = tx >> 3;
                    s_out[r * 2 + head] = ps;
                    t_out[r * 2 + head] = pt;
                }
            } else {
#pragma unroll
                for (int off = 8; off; off >>= 1) {
                    ps += __shfl_xor_sync(0xFFFFFFFFu, ps, off);
                    pt += __shfl_xor_sync(0xFFFFFFFFu, pt, off);
                }
                if (tx == 0 && r < M) {
                    s_out[r] = ps;
                    t_out[r] = pt;
                }
            }
        }

        if (r < M) {
#pragma unroll
            for (int j4 = 0; j4 < TN / 4; j4++) {
                int col = tx * TN + j4 * 4;
                float4 v;
                v.x = af[j4 * 4 + 0];
                v.y = af[j4 * 4 + 1];
                v.z = af[j4 * 4 + 2];
                v.w = af[j4 * 4 + 3];
                if (bias) {
                    v.x += bias[col + 0]; v.y += bias[col + 1];
                    v.z += bias[col + 2]; v.w += bias[col + 3];
                }
                if (relu) {
                    v.x = fmaxf(v.x, 0.f); v.y = fmaxf(v.y, 0.f);
                    v.z = fmaxf(v.z, 0.f); v.w = fmaxf(v.w, 0.f);
                }
                if (C2) {
                    float* dst = (col < 64) ? C : C2;
                    *reinterpret_cast<float4*>(&dst[(size_t)r * 64 + (col & 63)]) = v;
                } else {
                    *reinterpret_cast<float4*>(&C[(size_t)r * BN + col]) = v;
                }
            }
        }
    }
}

// ---------------- GAT aggregation: one WARP per dst node ----------------
template <int H, bool RELU>
__global__ void __launch_bounds__(256) k_aggw(const float* __restrict__ hin,
                                              const float* __restrict__ s,
                                              const float* __restrict__ t,
                                              const int* __restrict__ rowptr,
                                              const int* __restrict__ col,
                                              const float* __restrict__ bias,
                                              float* __restrict__ out, int n) {
    constexpr int W = H * 64;
    constexpr int C = W / 32;
    int node = (blockIdx.x * 256 + threadIdx.x) >> 5;
    if (node >= n) return;
    int lane = threadIdx.x & 31;
    int start = rowptr[node];
    int deg = rowptr[node + 1] - start;

    float tn[H];
#pragma unroll
    for (int h = 0; h < H; h++) tn[h] = t[node * H + h];

    // pass 1: max
    float m[H];
#pragma unroll
    for (int h = 0; h < H; h++) m[h] = -1e30f;
    for (int k = lane; k < deg; k += 32) {
        int src = col[start + k];
        if (H == 2) {
            float2 sv = *reinterpret_cast<const float2*>(&s[src * 2]);
            float e0 = sv.x + tn[0];
            e0 = e0 > 0.f ? e0 : NEG_SLOPE * e0;
            m[0] = fmaxf(m[0], e0);
            float e1 = sv.y + tn[1];
            e1 = e1 > 0.f ? e1 : NEG_SLOPE * e1;
            m[1] = fmaxf(m[1], e1);
        } else {
            float e = s[src] + tn[0];
            e = e > 0.f ? e : NEG_SLOPE * e;
            m[0] = fmaxf(m[0], e);
        }
    }
#pragma unroll
    for (int h = 0; h < H; h++)
#pragma unroll
        for (int off = 16; off; off >>= 1)
            m[h] = fmaxf(m[h], __shfl_xor_sync(0xFFFFFFFFu, m[h], off));

    // pass 2: sum of exp
    float sm[H];
#pragma unroll
    for (int h = 0; h < H; h++) sm[h] = 0.f;
    for (int k = lane; k < deg; k += 32) {
        int src = col[start + k];
        if (H == 2) {
            float2 sv = *reinterpret_cast<const float2*>(&s[src * 2]);
            float e0 = sv.x + tn[0];
            e0 = e0 > 0.f ? e0 : NEG_SLOPE * e0;
            sm[0] += __expf(e0 - m[0]);
            float e1 = sv.y + tn[1];
            e1 = e1 > 0.f ? e1 : NEG_SLOPE * e1;
            sm[1] += __expf(e1 - m[1]);
        } else {
            float e = s[src] + tn[0];
            e = e > 0.f ? e : NEG_SLOPE * e;
            sm[0] += __expf(e - m[0]);
        }
    }
    float inv[H];
#pragma unroll
    for (int h = 0; h < H; h++) {
#pragma unroll
        for (int off = 16; off; off >>= 1)
            sm[h] += __shfl_xor_sync(0xFFFFFFFFu, sm[h], off);
        inv[h] = 1.f / (sm[h] + 1e-16f);
    }

    // pass 3: weighted gather, 32-edge chunks broadcast via shfl
    float acc[C];
#pragma unroll
    for (int c = 0; c < C; c++) acc[c] = 0.f;
    for (int base = 0; base < deg; base += 32) {
        int k = base + lane;
        int src = 0;
        float al0 = 0.f, al1 = 0.f;
        if (k < deg) {
            src = col[start + k];
            if (H == 2) {
                float2 sv = *reinterpret_cast<const float2*>(&s[src * 2]);
                float e0 = sv.x + tn[0];
                e0 = e0 > 0.f ? e0 : NEG_SLOPE * e0;
                al0 = __expf(e0 - m[0]) * inv[0];
                float e1 = sv.y + tn[1];
                e1 = e1 > 0.f ? e1 : NEG_SLOPE * e1;
                al1 = __expf(e1 - m[1]) * inv[1];
            } else {
                float e = s[src] + tn[0];
                e = e > 0.f ? e : NEG_SLOPE * e;
                al0 = __expf(e - m[0]) * inv[0];
            }
        }
        int nk = min(32, deg - base);
        for (int e2 = 0; e2 < nk; e2++) {
            int sb = __shfl_sync(0xFFFFFFFFu, src, e2);
            float a0 = __shfl_sync(0xFFFFFFFFu, al0, e2);
            float a1 = (H == 2) ? __shfl_sync(0xFFFFFFFFu, al1, e2) : a0;
            const float* hp = hin + (size_t)sb * W;
#pragma unroll
            for (int c = 0; c < C; c++) {
                float a = (H == 2) ? ((c < 2) ? a0 : a1) : a0;
                acc[c] = fmaf(a, hp[lane + 32 * c], acc[c]);
            }
        }
    }

#pragma unroll
    for (int c = 0; c < C; c++) {
        float v = acc[c] + bias[lane + 32 * c];
        if (RELU) v = fmaxf(v, 0.f);
        out[(size_t)node * W + lane + 32 * c] = v;
    }
}

// ---------------- host launch ----------------
extern "C" void kernel_launch(void* const* d_in, const int* in_sizes, int n_in,
                              void* d_out, int out_size) {
    const float* x     = (const float*)d_in[0];
    const int*   ei    = (const int*)d_in[1];
    const float* W0    = (const float*)d_in[2];
    const float* as0   = (const float*)d_in[3];
    const float* ad0   = (const float*)d_in[4];
    const float* b0    = (const float*)d_in[5];
    const float* W1    = (const float*)d_in[6];
    const float* as1   = (const float*)d_in[7];
    const float* ad1   = (const float*)d_in[8];
    const float* b1    = (const float*)d_in[9];
    const float* W2    = (const float*)d_in[10];
    const float* as2   = (const float*)d_in[11];
    const float* ad2   = (const float*)d_in[12];
    const float* b2    = (const float*)d_in[13];
    const float* Wv    = (const float*)d_in[14];
    const float* bv    = (const float*)d_in[15];
    const float* Wt    = (const float*)d_in[16];
    const float* bt    = (const float*)d_in[17];

    int N = in_sizes[0] / 512;
    int E = in_sizes[1] / 2;

    float* out = (float*)d_out;
    float* h_out = out;
    float* vis = out + (size_t)N * 64;
    float* txt = out + (size_t)N * 64 * 2;

    float *h0, *h1, *sA, *tA, *Wcat, *bcat;
    int *deg, *rowptr, *cursor, *colA, *bsum, *bexc;
    cudaGetSymbolAddress((void**)&h0, g_h0);
    cudaGetSymbolAddress((void**)&h1, g_h1);
    cudaGetSymbolAddress((void**)&sA, g_s);
    cudaGetSymbolAddress((void**)&tA, g_t);
    cudaGetSymbolAddress((void**)&deg, g_deg);
    cudaGetSymbolAddress((void**)&rowptr, g_rowptr);
    cudaGetSymbolAddress((void**)&cursor, g_cursor);
    cudaGetSymbolAddress((void**)&colA, g_col);
    cudaGetSymbolAddress((void**)&bsum, g_bsum);
    cudaGetSymbolAddress((void**)&bexc, g_bexc);
    cudaGetSymbolAddress((void**)&Wcat, g_Wcat);
    cudaGetSymbolAddress((void**)&bcat, g_bcat);

    // side stream + events for capture-legal fork/join (created once)
    static cudaStream_t s2 = nullptr;
    static cudaEvent_t evFork = nullptr, evJoin = nullptr;
    if (!s2) {
        cudaStreamCreateWithFlags(&s2, cudaStreamNonBlocking);
        cudaEventCreateWithFlags(&evFork, cudaEventDisableTiming);
        cudaEventCreateWithFlags(&evJoin, cudaEventDisableTiming);
    }

    int nb = (N + 255) / 256;
    int gblk = (N + 127) / 128;
    int wgrid = (N * 32 + 255) / 256;

    // ---- fork: CSR build + Wcat prep on side stream ----
    cudaEventRecord(evFork, 0);
    cudaStreamWaitEvent(s2, evFork, 0);
    k_init_deg<<<nb, 256, 0, s2>>>(deg, N);
    k_hist<<<(E + 255) / 256, 256, 0, s2>>>(ei, E, deg);
    k_blocksums<<<nb, 256, 0, s2>>>(deg, bsum, N);
    k_scan_top<<<1, 256, 0, s2>>>(bsum, bexc, nb);
    k_scan_apply<<<nb, 256, 0, s2>>>(deg, bexc, rowptr, cursor, colA, N);
    k_scatter<<<(E + 255) / 256, 256, 0, s2>>>(ei, E, cursor, colA);
    k_prep<<<(64 * 128 + 255) / 256, 256, 0, s2>>>(Wv, bv, Wt, bt, Wcat, bcat);
    cudaEventRecord(evJoin, s2);

    // ---- main stream: layer-0 GEMM concurrently ----
    k_gemm<128><<<gblk, 256>>>(x, W0, h0, nullptr, N, 512, nullptr, 0, as0, ad0, sA, tA);

    // ---- join ----
    cudaStreamWaitEvent(0, evJoin, 0);

    // ---- layer 0 aggregation ----
    k_aggw<2, true><<<wgrid, 256>>>(h0, sA, tA, rowptr, colA, b0, h1, N);

    // ---- layer 1 ----
    k_gemm<128><<<gblk, 256>>>(h1, W1, h0, nullptr, N, 128, nullptr, 0, as1, ad1, sA, tA);
    k_aggw<2, true><<<wgrid, 256>>>(h0, sA, tA, rowptr, colA, b1, h1, N);

    // ---- layer 2 (heads=1, no relu) ----
    k_gemm<64><<<gblk, 256>>>(h1, W2, h0, nullptr, N, 128, nullptr, 0, as2, ad2, sA, tA);
    k_aggw<1, false><<<wgrid, 256>>>(h0, sA, tA, rowptr, colA, b2, h_out, N);

    // ---- MLP heads: one combined GEMM with split store ----
    k_gemm<128><<<gblk, 256>>>(h_out, Wcat, vis, txt, N, 64, bcat, 1,
                               nullptr, nullptr, nullptr, nullptr);
}

// round 8
// speedup vs baseline: 2.2883x; 1.0310x over previous
#include <cuda_runtime.h>
#include <cstdint>

#define NNODES 50000
#define NEDGES 800000
#define TOTEDGES (NEDGES + NNODES)
#define NEG_SLOPE 0.2f

// ---------------- scratch (allocation-free: device globals) ----------------
__device__ float g_h0[(size_t)NNODES * 128];
__device__ float g_h1[(size_t)NNODES * 128];
__device__ float g_s[NNODES * 2];
__device__ float g_t[NNODES * 2];
__device__ int   g_deg[NNODES];
__device__ int   g_rowptr[NNODES + 1];
__device__ int   g_cursor[NNODES];
__device__ int   g_col[TOTEDGES];
__device__ int   g_bsum[256];
__device__ int   g_bexc[256];
__device__ float g_Wcat[64 * 128];
__device__ float g_bcat[128];

// ---------------- helpers ----------------
__device__ __forceinline__ uint32_t smem_u32(const void* p) {
    return (uint32_t)__cvta_generic_to_shared(p);
}
typedef unsigned long long ull;
union F4U { float4 f; ull u[2]; };
__device__ __forceinline__ ull splat2(float x) {
    ull r;
    asm("mov.b64 %0, {%1, %1};" : "=l"(r) : "f"(x));
    return r;
}
__device__ __forceinline__ void fma2(ull& d, ull a, ull b) {
    asm("fma.rn.f32x2 %0, %1, %2, %3;" : "=l"(d) : "l"(a), "l"(b), "l"(d));
}
__device__ __forceinline__ void upk2(ull v, float& lo, float& hi) {
    asm("mov.b64 {%0, %1}, %2;" : "=f"(lo), "=f"(hi) : "l"(v));
}
__device__ __forceinline__ void cpa16(uint32_t dst, const void* src) {
    asm volatile("cp.async.cg.shared.global [%0], [%1], 16;" :: "r"(dst), "l"(src));
}

// ---------------- CSR build ----------------
__global__ void k_init_deg(int* __restrict__ deg, int n) {
    int i = blockIdx.x * blockDim.x + threadIdx.x;
    if (i < n) deg[i] = 1;
}
__global__ void k_hist(const int* __restrict__ ei, int e, int* __restrict__ deg) {
    int i = blockIdx.x * blockDim.x + threadIdx.x;
    if (i < e) atomicAdd(&deg[ei[e + i]], 1);
}
__global__ void k_blocksums(const int* __restrict__ deg, int* __restrict__ bsum, int n) {
    __shared__ int wred[8];
    int i = blockIdx.x * 256 + threadIdx.x;
    int v = (i < n) ? deg[i] : 0;
    int lane = threadIdx.x & 31, w = threadIdx.x >> 5;
#pragma unroll
    for (int off = 16; off; off >>= 1) v += __shfl_xor_sync(0xFFFFFFFFu, v, off);
    if (lane == 0) wred[w] = v;
    __syncthreads();
    if (threadIdx.x == 0) {
        int s = 0;
#pragma unroll
        for (int k = 0; k < 8; k++) s += wred[k];
        bsum[blockIdx.x] = s;
    }
}
__global__ void k_scan_top(const int* __restrict__ bsum, int* __restrict__ bexc, int nb) {
    __shared__ int wred[8];
    int tid = threadIdx.x, lane = tid & 31, w = tid >> 5;
    int v = (tid < nb) ? bsum[tid] : 0;
    int x = v;
#pragma unroll
    for (int off = 1; off < 32; off <<= 1) {
        int y = __shfl_up_sync(0xFFFFFFFFu, x, off);
        if (lane >= off) x += y;
    }
    if (lane == 31) wred[w] = x;
    __syncthreads();
    if (w == 0) {
        int sv = (lane < 8) ? wred[lane] : 0;
#pragma unroll
        for (int off = 1; off < 8; off <<= 1) {
            int y = __shfl_up_sync(0xFFFFFFFFu, sv, off);
            if (lane >= off) sv += y;
        }
        if (lane < 8) wred[lane] = sv;
    }
    __syncthreads();
    int woff = (w > 0) ? wred[w - 1] : 0;
    if (tid < nb) bexc[tid] = x + woff - v;
}
__global__ void k_scan_apply(const int* __restrict__ deg, const int* __restrict__ bexc,
                             int* __restrict__ rowptr, int* __restrict__ cursor,
                             int* __restrict__ col, int n) {
    __shared__ int wred[8];
    int i = blockIdx.x * 256 + threadIdx.x;
    int tid = threadIdx.x, lane = tid & 31, w = tid >> 5;
    int v = (i < n) ? deg[i] : 0;
    int x = v;
#pragma unroll
    for (int off = 1; off < 32; off <<= 1) {
        int y = __shfl_up_sync(0xFFFFFFFFu, x, off);
        if (lane >= off) x += y;
    }
    if (lane == 31) wred[w] = x;
    __syncthreads();
    if (w == 0) {
        int sv = (lane < 8) ? wred[lane] : 0;
#pragma unroll
        for (int off = 1; off < 8; off <<= 1) {
            int y = __shfl_up_sync(0xFFFFFFFFu, sv, off);
            if (lane >= off) sv += y;
        }
        if (lane < 8) wred[lane] = sv;
    }
    __syncthreads();
    int woff = (w > 0) ? wred[w - 1] : 0;
    if (i < n) {
        int incl = x + woff + bexc[blockIdx.x];
        rowptr[i + 1] = incl;
        int p = incl - v;
        col[p] = i;
        cursor[i] = p + 1;
        if (i == 0) rowptr[0] = 0;
    }
}
__global__ void k_scatter(const int* __restrict__ ei, int e, int* __restrict__ cursor,
                          int* __restrict__ col) {
    int i = blockIdx.x * blockDim.x + threadIdx.x;
    if (i < e) {
        int s = ei[i];
        int d = ei[e + i];
        int p = atomicAdd(&cursor[d], 1);
        col[p] = s;
    }
}

// ---------------- Wcat prep ----------------
__global__ void k_prep(const float* __restrict__ Wv, const float* __restrict__ bv,
                       const float* __restrict__ Wt, const float* __restrict__ bt,
                       float* __restrict__ Wcat, float* __restrict__ bcat) {
    int i = blockIdx.x * blockDim.x + threadIdx.x;
    if (i < 64 * 128) {
        int k = i >> 7, n = i & 127;
        Wcat[i] = (n < 64) ? Wv[k * 64 + n] : Wt[k * 64 + (n - 64)];
    }
    if (i < 128) bcat[i] = (i < 64) ? bv[i] : bt[i - 64];
}

// ---------------- f32x2 GEMM: C[M,BN] = A[M,K] @ B[K,BN] ----------------
// Thread (tx,ty) owns rows ty*8+i and cols {g*64 + tx*4 + j} for g groups.
// B reads are float4 at 16B thread-stride -> bank-conflict-free.
template <int BN>
__global__ void __launch_bounds__(256, 2) k_gemm(
    const float* __restrict__ A, const float* __restrict__ B,
    float* __restrict__ C, float* __restrict__ C2, int M, int K,
    const float* __restrict__ bias, int relu,
    const float* __restrict__ a_src, const float* __restrict__ a_dst,
    float* __restrict__ s_out, float* __restrict__ t_out)
{
    constexpr int BM = 128, BK = 16, TN = BN / 16;
    constexpr int NG = BN / 64;  // column groups per thread (1 or 2)
    __shared__ float As[2][BM][BK];
    __shared__ float Bs[2][BK][BN];
    __shared__ float sh_att[2 * BN];

    int tid = threadIdx.x;
    int tx = tid & 15, ty = tid >> 4;
    int blockRow = blockIdx.x * BM;

    if (a_src) {
        if (tid < BN) sh_att[tid] = a_src[tid];
        else if (tid < 2 * BN) sh_att[tid] = a_dst[tid - BN];
    }

    ull acc[8][TN / 2];
#pragma unroll
    for (int i = 0; i < 8; i++)
#pragma unroll
        for (int j = 0; j < TN / 2; j++) acc[i][j] = 0ull;

    int nch = K / BK;

    auto loadA = [&](int c, int st) {
        int k0 = c * BK;
#pragma unroll
        for (int l = 0; l < 2; l++) {
            int f = tid + l * 256;
            int row = f >> 2, q = f & 3;
            int gr = blockRow + row;
            if (gr >= M) gr = M - 1;
            cpa16(smem_u32(&As[st][row][q * 4]), &A[(size_t)gr * K + k0 + q * 4]);
        }
    };
    auto loadB = [&](int c, int st) {
        int k0 = c * BK;
        constexpr int CH = BK * BN / 4;
#pragma unroll
        for (int l = 0; l < CH / 256; l++) {
            int f = tid + l * 256;
            int kr = f / (BN / 4), q = f % (BN / 4);
            cpa16(smem_u32(&Bs[st][kr][q * 4]), &B[(size_t)(k0 + kr) * BN + q * 4]);
        }
    };

    loadA(0, 0);
    loadB(0, 0);
    asm volatile("cp.async.commit_group;");

    for (int c = 0; c < nch; c++) {
        int st = c & 1;
        if (c + 1 < nch) {
            loadA(c + 1, (c + 1) & 1);
            loadB(c + 1, (c + 1) & 1);
            asm volatile("cp.async.commit_group;");
            asm volatile("cp.async.wait_group 1;");
        } else {
            asm volatile("cp.async.wait_group 0;");
        }
        __syncthreads();

#pragma unroll
        for (int k4 = 0; k4 < BK; k4 += 4) {
            float4 a4[8];
#pragma unroll
            for (int i = 0; i < 8; i++)
                a4[i] = *reinterpret_cast<const float4*>(&As[st][ty * 8 + i][k4]);
#pragma unroll
            for (int kk = 0; kk < 4; kk++) {
                ull b2[TN / 2];
#pragma unroll
                for (int g = 0; g < NG; g++) {
                    F4U bu;
                    bu.f = *reinterpret_cast<const float4*>(&Bs[st][k4 + kk][g * 64 + tx * 4]);
                    b2[g * 2 + 0] = bu.u[0];
                    b2[g * 2 + 1] = bu.u[1];
                }
#pragma unroll
                for (int i = 0; i < 8; i++) {
                    float av = (kk == 0) ? a4[i].x : (kk == 1) ? a4[i].y : (kk == 2) ? a4[i].z : a4[i].w;
                    ull a2 = splat2(av);
#pragma unroll
                    for (int j = 0; j < TN / 2; j++) fma2(acc[i][j], a2, b2[j]);
                }
            }
        }
        __syncthreads();
    }

    // ---- per-row epilogue ----
#pragma unroll
    for (int i = 0; i < 8; i++) {
        int r = blockRow + ty * 8 + i;
        float af[TN];
#pragma unroll
        for (int j = 0; j < TN / 2; j++) upk2(acc[i][j], af[2 * j], af[2 * j + 1]);

        if (s_out) {
            if (BN == 128) {
                // group g == head g: af[g*4+j] is col g*64 + tx*4 + j
                float ps0 = 0.f, pt0 = 0.f, ps1 = 0.f, pt1 = 0.f;
#pragma unroll
                for (int j = 0; j < 4; j++) {
                    int c0 = tx * 4 + j, c1 = 64 + tx * 4 + j;
                    ps0 += af[j] * sh_att[c0];
                    pt0 += af[j] * sh_att[BN + c0];
                    ps1 += af[4 + j] * sh_att[c1];
                    pt1 += af[4 + j] * sh_att[BN + c1];
                }
#pragma unroll
                for (int off = 8; off; off >>= 1) {
                    ps0 += __shfl_xor_sync(0xFFFFFFFFu, ps0, off);
                    pt0 += __shfl_xor_sync(0xFFFFFFFFu, pt0, off);
                    ps1 += __shfl_xor_sync(0xFFFFFFFFu, ps1, off);
                    pt1 += __shfl_xor_sync(0xFFFFFFFFu, pt1, off);
                }
                if (tx == 0 && r < M) {
                    s_out[r * 2 + 0] = ps0;
                    s_out[r * 2 + 1] = ps1;
                    t_out[r * 2 + 0] = pt0;
                    t_out[r * 2 + 1] = pt1;
                }
            } else {
                float ps = 0.f, pt = 0.f;
#pragma unroll
                for (int j = 0; j < 4; j++) {
                    int col = tx * 4 + j;
                    ps += af[j] * sh_att[col];
                    pt += af[j] * sh_att[BN + col];
                }
#pragma unroll
                for (int off = 8; off; off >>= 1) {
                    ps += __shfl_xor_sync(0xFFFFFFFFu, ps, off);
                    pt += __shfl_xor_sync(0xFFFFFFFFu, pt, off);
                }
                if (tx == 0 && r < M) {
                    s_out[r] = ps;
                    t_out[r] = pt;
                }
            }
        }

        if (r < M) {
#pragma unroll
            for (int g = 0; g < NG; g++) {
                int col = g * 64 + tx * 4;
                float4 v;
                v.x = af[g * 4 + 0];
                v.y = af[g * 4 + 1];
                v.z = af[g * 4 + 2];
                v.w = af[g * 4 + 3];
                if (bias) {
                    v.x += bias[col + 0]; v.y += bias[col + 1];
                    v.z += bias[col + 2]; v.w += bias[col + 3];
                }
                if (relu) {
                    v.x = fmaxf(v.x, 0.f); v.y = fmaxf(v.y, 0.f);
                    v.z = fmaxf(v.z, 0.f); v.w = fmaxf(v.w, 0.f);
                }
                if (C2) {
                    float* dst = (g == 0) ? C : C2;
                    *reinterpret_cast<float4*>(&dst[(size_t)r * 64 + tx * 4]) = v;
                } else {
                    *reinterpret_cast<float4*>(&C[(size_t)r * BN + col]) = v;
                }
            }
        }
    }
}

// ---------------- GAT aggregation: one WARP per dst node (online softmax) ----
template <int H, bool RELU>
__global__ void __launch_bounds__(256) k_aggw(const float* __restrict__ hin,
                                              const float* __restrict__ s,
                                              const float* __restrict__ t,
                                              const int* __restrict__ rowptr,
                                              const int* __restrict__ col,
                                              const float* __restrict__ bias,
                                              float* __restrict__ out, int n) {
    constexpr int W = H * 64;
    constexpr int C = W / 32;
    int node = (blockIdx.x * 256 + threadIdx.x) >> 5;
    if (node >= n) return;
    int lane = threadIdx.x & 31;
    int start = rowptr[node];
    int deg = rowptr[node + 1] - start;

    float tn[H];
#pragma unroll
    for (int h = 0; h < H; h++) tn[h] = t[node * H + h];

    // fused pass 1+2: online softmax (running max + rescaled sum)
    float m[H], sm[H];
#pragma unroll
    for (int h = 0; h < H; h++) { m[h] = -1e30f; sm[h] = 0.f; }
    for (int k = lane; k < deg; k += 32) {
        int src = col[start + k];
        float e[H];
        if (H == 2) {
            float2 sv = *reinterpret_cast<const float2*>(&s[src * 2]);
            e[0] = sv.x + tn[0];
            e[1] = sv.y + tn[1];
        } else {
            e[0] = s[src] + tn[0];
        }
#pragma unroll
        for (int h = 0; h < H; h++) {
            float eh = e[h];
            eh = eh > 0.f ? eh : NEG_SLOPE * eh;
            float old = m[h];
            float nm = fmaxf(old, eh);
            sm[h] = sm[h] * __expf(old - nm) + __expf(eh - nm);
            m[h] = nm;
        }
    }
    // cross-lane merge
    float inv[H];
#pragma unroll
    for (int h = 0; h < H; h++) {
#pragma unroll
        for (int off = 16; off; off >>= 1) {
            float mo = __shfl_xor_sync(0xFFFFFFFFu, m[h], off);
            float so = __shfl_xor_sync(0xFFFFFFFFu, sm[h], off);
            float nm = fmaxf(m[h], mo);
            sm[h] = sm[h] * __expf(m[h] - nm) + so * __expf(mo - nm);
            m[h] = nm;
        }
        inv[h] = 1.f / (sm[h] + 1e-16f);
    }

    // pass 3: weighted gather, 32-edge chunks broadcast via shfl
    float acc[C];
#pragma unroll
    for (int c = 0; c < C; c++) acc[c] = 0.f;
    for (int base = 0; base < deg; base += 32) {
        int k = base + lane;
        int src = 0;
        float al0 = 0.f, al1 = 0.f;
        if (k < deg) {
            src = col[start + k];
            if (H == 2) {
                float2 sv = *reinterpret_cast<const float2*>(&s[src * 2]);
                float e0 = sv.x + tn[0];
                e0 = e0 > 0.f ? e0 : NEG_SLOPE * e0;
                al0 = __expf(e0 - m[0]) * inv[0];
                float e1 = sv.y + tn[1];
                e1 = e1 > 0.f ? e1 : NEG_SLOPE * e1;
                al1 = __expf(e1 - m[1]) * inv[1];
            } else {
                float e = s[src] + tn[0];
                e = e > 0.f ? e : NEG_SLOPE * e;
                al0 = __expf(e - m[0]) * inv[0];
            }
        }
        int nk = min(32, deg - base);
        for (int e2 = 0; e2 < nk; e2++) {
            int sb = __shfl_sync(0xFFFFFFFFu, src, e2);
            float a0 = __shfl_sync(0xFFFFFFFFu, al0, e2);
            float a1 = (H == 2) ? __shfl_sync(0xFFFFFFFFu, al1, e2) : a0;
            const float* hp = hin + (size_t)sb * W;
#pragma unroll
            for (int c = 0; c < C; c++) {
                float a = (H == 2) ? ((c < 2) ? a0 : a1) : a0;
                acc[c] = fmaf(a, hp[lane + 32 * c], acc[c]);
            }
        }
    }

#pragma unroll
    for (int c = 0; c < C; c++) {
        float v = acc[c] + bias[lane + 32 * c];
        if (RELU) v = fmaxf(v, 0.f);
        out[(size_t)node * W + lane + 32 * c] = v;
    }
}

// ---------------- host launch ----------------
extern "C" void kernel_launch(void* const* d_in, const int* in_sizes, int n_in,
                              void* d_out, int out_size) {
    const float* x     = (const float*)d_in[0];
    const int*   ei    = (const int*)d_in[1];
    const float* W0    = (const float*)d_in[2];
    const float* as0   = (const float*)d_in[3];
    const float* ad0   = (const float*)d_in[4];
    const float* b0    = (const float*)d_in[5];
    const float* W1    = (const float*)d_in[6];
    const float* as1   = (const float*)d_in[7];
    const float* ad1   = (const float*)d_in[8];
    const float* b1    = (const float*)d_in[9];
    const float* W2    = (const float*)d_in[10];
    const float* as2   = (const float*)d_in[11];
    const float* ad2   = (const float*)d_in[12];
    const float* b2    = (const float*)d_in[13];
    const float* Wv    = (const float*)d_in[14];
    const float* bv    = (const float*)d_in[15];
    const float* Wt    = (const float*)d_in[16];
    const float* bt    = (const float*)d_in[17];

    int N = in_sizes[0] / 512;
    int E = in_sizes[1] / 2;

    float* out = (float*)d_out;
    float* h_out = out;
    float* vis = out + (size_t)N * 64;
    float* txt = out + (size_t)N * 64 * 2;

    float *h0, *h1, *sA, *tA, *Wcat, *bcat;
    int *deg, *rowptr, *cursor, *colA, *bsum, *bexc;
    cudaGetSymbolAddress((void**)&h0, g_h0);
    cudaGetSymbolAddress((void**)&h1, g_h1);
    cudaGetSymbolAddress((void**)&sA, g_s);
    cudaGetSymbolAddress((void**)&tA, g_t);
    cudaGetSymbolAddress((void**)&deg, g_deg);
    cudaGetSymbolAddress((void**)&rowptr, g_rowptr);
    cudaGetSymbolAddress((void**)&cursor, g_cursor);
    cudaGetSymbolAddress((void**)&colA, g_col);
    cudaGetSymbolAddress((void**)&bsum, g_bsum);
    cudaGetSymbolAddress((void**)&bexc, g_bexc);
    cudaGetSymbolAddress((void**)&Wcat, g_Wcat);
    cudaGetSymbolAddress((void**)&bcat, g_bcat);

    static cudaStream_t s2 = nullptr;
    static cudaEvent_t evFork = nullptr, evJoin = nullptr;
    if (!s2) {
        cudaStreamCreateWithFlags(&s2, cudaStreamNonBlocking);
        cudaEventCreateWithFlags(&evFork, cudaEventDisableTiming);
        cudaEventCreateWithFlags(&evJoin, cudaEventDisableTiming);
    }

    int nb = (N + 255) / 256;
    int gblk = (N + 127) / 128;
    int wgrid = (N * 32 + 255) / 256;

    // ---- fork: CSR build + Wcat prep on side stream ----
    cudaEventRecord(evFork, 0);
    cudaStreamWaitEvent(s2, evFork, 0);
    k_init_deg<<<nb, 256, 0, s2>>>(deg, N);
    k_hist<<<(E + 255) / 256, 256, 0, s2>>>(ei, E, deg);
    k_blocksums<<<nb, 256, 0, s2>>>(deg, bsum, N);
    k_scan_top<<<1, 256, 0, s2>>>(bsum, bexc, nb);
    k_scan_apply<<<nb, 256, 0, s2>>>(deg, bexc, rowptr, cursor, colA, N);
    k_scatter<<<(E + 255) / 256, 256, 0, s2>>>(ei, E, cursor, colA);
    k_prep<<<(64 * 128 + 255) / 256, 256, 0, s2>>>(Wv, bv, Wt, bt, Wcat, bcat);
    cudaEventRecord(evJoin, s2);

    // ---- main stream: layer-0 GEMM concurrently ----
    k_gemm<128><<<gblk, 256>>>(x, W0, h0, nullptr, N, 512, nullptr, 0, as0, ad0, sA, tA);

    // ---- join ----
    cudaStreamWaitEvent(0, evJoin, 0);

    // ---- layer 0 aggregation ----
    k_aggw<2, true><<<wgrid, 256>>>(h0, sA, tA, rowptr, colA, b0, h1, N);

    // ---- layer 1 ----
    k_gemm<128><<<gblk, 256>>>(h1, W1, h0, nullptr, N, 128, nullptr, 0, as1, ad1, sA, tA);
    k_aggw<2, true><<<wgrid, 256>>>(h0, sA, tA, rowptr, colA, b1, h1, N);

    // ---- layer 2 (heads=1, no relu) ----
    k_gemm<64><<<gblk, 256>>>(h1, W2, h0, nullptr, N, 128, nullptr, 0, as2, ad2, sA, tA);
    k_aggw<1, false><<<wgrid, 256>>>(h0, sA, tA, rowptr, colA, b2, h_out, N);

    // ---- MLP heads: one combined GEMM with split store ----
    k_gemm<128><<<gblk, 256>>>(h_out, Wcat, vis, txt, N, 64, bcat, 1,
                               nullptr, nullptr, nullptr, nullptr);
}